// round 2
// baseline (speedup 1.0000x reference)
#include <cuda_runtime.h>

#define TB 64
#define NTHREADS 256

// smem layout (floats):
//  Ws1  [64][257]  = 16448
//  Wihs [192][65]  = 12480
//  Whhs [192][65]  = 12480
//  Xs   [64][65]   =  4160
//  Hs   [64][65]   =  4160
//  Os   [64][65]   =  4160
//  bihs 192, bhhs 192, bf1s 64, wf2s 64
#define SMEM_FLOATS (64*257 + 2*192*65 + 3*64*65 + 192 + 192 + 64 + 64)
#define SMEM_BYTES  (SMEM_FLOATS * 4)

__device__ __forceinline__ float fast_sigmoid(float x) {
    return __fdividef(1.0f, 1.0f + __expf(-x));
}
__device__ __forceinline__ float fast_tanh(float x) {
    // 1 - 2/(e^{2x}+1); saturates correctly at +-1 via inf/0 behavior
    return 1.0f - __fdividef(2.0f, __expf(2.0f * x) + 1.0f);
}

__global__ __launch_bounds__(NTHREADS, 1)
void gru_critic_kernel(
    const float* __restrict__ obs,        // [B,256]
    const float* __restrict__ hin,        // [B,64]
    const int* __restrict__ mask,         // [B] (bool upcast to int32 by harness)
    const float* __restrict__ Wfc1,       // [64,256]
    const float* __restrict__ bfc1,       // [64]
    const float* __restrict__ wih,        // [192,64]
    const float* __restrict__ whh,        // [192,64]
    const float* __restrict__ bih,        // [192]
    const float* __restrict__ bhh,        // [192]
    const float* __restrict__ Wfc2,       // [64]
    const float* __restrict__ bfc2,       // [1]
    float* __restrict__ value_out,        // [B]
    float* __restrict__ hout)             // [B,64]
{
    extern __shared__ float sm[];
    float* Ws1  = sm;                       // [64][257]
    float* Wihs = Ws1  + 64 * 257;          // [192][65]
    float* Whhs = Wihs + 192 * 65;          // [192][65]
    float* Xs   = Whhs + 192 * 65;          // [64][65]
    float* Hs   = Xs   + 64 * 65;           // [64][65]
    float* Os   = Hs   + 64 * 65;           // [64][65]
    float* bihs = Os   + 64 * 65;           // [192]
    float* bhhs = bihs + 192;               // [192]
    float* bf1s = bhhs + 192;               // [64]
    float* wf2s = bf1s + 64;                // [64]

    const int tid  = threadIdx.x;
    const int row0 = blockIdx.x * TB;
    const int tr   = tid >> 4;              // 0..15 -> rows 4*tr..4*tr+3
    const int tc   = tid & 15;              // 0..15 -> cols 4*tc..4*tc+3

    // ---- load weights / biases / H tile into smem ----
    for (int i = tid; i < 64 * 256; i += NTHREADS) {
        int c = i >> 8, k = i & 255;
        Ws1[c * 257 + k] = Wfc1[i];
    }
    for (int i = tid; i < 192 * 64; i += NTHREADS) {
        int j = i >> 6, k = i & 63;
        Wihs[j * 65 + k] = wih[i];
        Whhs[j * 65 + k] = whh[i];
    }
    for (int i = tid; i < 192; i += NTHREADS) { bihs[i] = bih[i]; bhhs[i] = bhh[i]; }
    if (tid < 64) { bf1s[tid] = bfc1[tid]; wf2s[tid] = Wfc2[tid]; }
    for (int i = tid; i < 64 * 64; i += NTHREADS) {
        int r = i >> 6, c = i & 63;
        Hs[r * 65 + c] = hin[(size_t)(row0 + r) * 64 + c];
    }

    // ---- phase 1: X = tanh(obs @ Wfc1^T + b) over K=256 in 4 chunks of 64 ----
    float acc[4][4];
#pragma unroll
    for (int a = 0; a < 4; ++a)
#pragma unroll
        for (int b = 0; b < 4; ++b) acc[a][b] = 0.0f;

    for (int kc = 0; kc < 4; ++kc) {
        __syncthreads();  // previous chunk consumed (and, on kc=0, weights/H written)
        for (int i = tid; i < 64 * 64; i += NTHREADS) {
            int r = i >> 6, k = i & 63;
            Os[r * 65 + k] = obs[(size_t)(row0 + r) * 256 + kc * 64 + k];
        }
        __syncthreads();
        const float* ob = Os  + 4 * tr * 65;
        const float* wp = Ws1 + 4 * tc * 257 + kc * 64;
#pragma unroll 4
        for (int k = 0; k < 64; ++k) {
            float o0 = ob[k], o1 = ob[65 + k], o2 = ob[130 + k], o3 = ob[195 + k];
            float w0 = wp[k], w1 = wp[257 + k], w2 = wp[514 + k], w3 = wp[771 + k];
            acc[0][0] += o0 * w0; acc[0][1] += o0 * w1; acc[0][2] += o0 * w2; acc[0][3] += o0 * w3;
            acc[1][0] += o1 * w0; acc[1][1] += o1 * w1; acc[1][2] += o1 * w2; acc[1][3] += o1 * w3;
            acc[2][0] += o2 * w0; acc[2][1] += o2 * w1; acc[2][2] += o2 * w2; acc[2][3] += o2 * w3;
            acc[3][0] += o3 * w0; acc[3][1] += o3 * w1; acc[3][2] += o3 * w2; acc[3][3] += o3 * w3;
        }
    }
#pragma unroll
    for (int rr = 0; rr < 4; ++rr)
#pragma unroll
        for (int cc = 0; cc < 4; ++cc) {
            int j = 4 * tc + cc;
            Xs[(4 * tr + rr) * 65 + j] = fast_tanh(acc[rr][cc] + bf1s[j]);
        }
    __syncthreads();

    // ---- phase 2: GRU gate GEMMs (r,z merged ih+hh accumulators; n kept split) ----
    float ar[4][4], az[4][4], ain[4][4], ahn[4][4];
#pragma unroll
    for (int rr = 0; rr < 4; ++rr)
#pragma unroll
        for (int cc = 0; cc < 4; ++cc) {
            int j = 4 * tc + cc;
            ar[rr][cc]  = bihs[j]       + bhhs[j];
            az[rr][cc]  = bihs[64 + j]  + bhhs[64 + j];
            ain[rr][cc] = bihs[128 + j];
            ahn[rr][cc] = bhhs[128 + j];
        }

    const float* xb  = Xs + 4 * tr * 65;
    const float* hb  = Hs + 4 * tr * 65;
    const float* wir = Wihs + (4 * tc) * 65;
    const float* wiz = Wihs + (64 + 4 * tc) * 65;
    const float* win = Wihs + (128 + 4 * tc) * 65;
    const float* whr = Whhs + (4 * tc) * 65;
    const float* whz = Whhs + (64 + 4 * tc) * 65;
    const float* whn = Whhs + (128 + 4 * tc) * 65;

#pragma unroll 2
    for (int k = 0; k < 64; ++k) {
        float xv[4], hv[4];
#pragma unroll
        for (int rr = 0; rr < 4; ++rr) {
            xv[rr] = xb[rr * 65 + k];
            hv[rr] = hb[rr * 65 + k];
        }
#pragma unroll
        for (int cc = 0; cc < 4; ++cc) {
            float wri = wir[cc * 65 + k], wzi = wiz[cc * 65 + k], wni = win[cc * 65 + k];
            float wrh = whr[cc * 65 + k], wzh = whz[cc * 65 + k], wnh = whn[cc * 65 + k];
#pragma unroll
            for (int rr = 0; rr < 4; ++rr) {
                ar[rr][cc]  += xv[rr] * wri;
                ar[rr][cc]  += hv[rr] * wrh;
                az[rr][cc]  += xv[rr] * wzi;
                az[rr][cc]  += hv[rr] * wzh;
                ain[rr][cc] += xv[rr] * wni;
                ahn[rr][cc] += hv[rr] * wnh;
            }
        }
    }

    __syncthreads();  // all reads of Xs complete before we reuse it for new_h

    // ---- epilogue: gates, mask select, value head partials ----
    const float bias2 = bfc2[0];
    float vpart[4] = {0.0f, 0.0f, 0.0f, 0.0f};
    int mk[4];
#pragma unroll
    for (int rr = 0; rr < 4; ++rr) mk[rr] = mask[row0 + 4 * tr + rr];

#pragma unroll
    for (int rr = 0; rr < 4; ++rr) {
#pragma unroll
        for (int cc = 0; cc < 4; ++cc) {
            int j = 4 * tc + cc;
            float r = fast_sigmoid(ar[rr][cc]);
            float z = fast_sigmoid(az[rr][cc]);
            float n = fast_tanh(ain[rr][cc] + r * ahn[rr][cc]);
            float hold = hb[rr * 65 + j];
            float hg = (1.0f - z) * n + z * hold;
            float hn2 = mk[rr] ? hg : hold;
            Xs[(4 * tr + rr) * 65 + j] = hn2;   // stage for coalesced store
            vpart[rr] += hn2 * wf2s[j];
        }
    }

    // reduce value partials across the 16 threads (tc) sharing each row group
#pragma unroll
    for (int off = 8; off > 0; off >>= 1)
#pragma unroll
        for (int rr = 0; rr < 4; ++rr)
            vpart[rr] += __shfl_xor_sync(0xffffffffu, vpart[rr], off);
    if (tc == 0) {
#pragma unroll
        for (int rr = 0; rr < 4; ++rr)
            value_out[row0 + 4 * tr + rr] = vpart[rr] + bias2;
    }

    __syncthreads();
    // coalesced new_h store
    for (int i = tid; i < 64 * 64; i += NTHREADS) {
        int r = i >> 6, c = i & 63;
        hout[(size_t)(row0 + r) * 64 + c] = Xs[r * 65 + c];
    }
}

extern "C" void kernel_launch(void* const* d_in, const int* in_sizes, int n_in,
                              void* d_out, int out_size) {
    const float* obs = (const float*)d_in[0];
    const float* h1  = (const float*)d_in[1];
    const float* h2  = (const float*)d_in[2];
    const int*   mask = (const int*)d_in[3];

    const int B = in_sizes[1] / 64;   // 262144

    float* out = (float*)d_out;
    float* v1  = out;
    float* v2  = out + (size_t)B;
    float* ho1 = out + 2 * (size_t)B;
    float* ho2 = ho1 + (size_t)B * 64;

    cudaFuncSetAttribute(gru_critic_kernel,
                         cudaFuncAttributeMaxDynamicSharedMemorySize, SMEM_BYTES);

    dim3 grid(B / TB);
    gru_critic_kernel<<<grid, NTHREADS, SMEM_BYTES>>>(
        obs, h1, mask,
        (const float*)d_in[4],  (const float*)d_in[5],
        (const float*)d_in[6],  (const float*)d_in[7],
        (const float*)d_in[8],  (const float*)d_in[9],
        (const float*)d_in[10], (const float*)d_in[11],
        v1, ho1);
    gru_critic_kernel<<<grid, NTHREADS, SMEM_BYTES>>>(
        obs, h2, mask,
        (const float*)d_in[12], (const float*)d_in[13],
        (const float*)d_in[14], (const float*)d_in[15],
        (const float*)d_in[16], (const float*)d_in[17],
        (const float*)d_in[18], (const float*)d_in[19],
        v2, ho2);
}

// round 4
// speedup vs baseline: 3.5959x; 3.5959x over previous
#include <cuda_runtime.h>
#include <cuda_bf16.h>
#include <stdint.h>

#define NT 256

// ---------------- math helpers ----------------
__device__ __forceinline__ float fsigm(float x) { return __fdividef(1.0f, 1.0f + __expf(-x)); }
__device__ __forceinline__ float ftanh(float x) {
    return 1.0f - __fdividef(2.0f, __expf(2.0f * x) + 1.0f);
}
// split a,b into packed bf16 hi pair and lo (residual) pair
__device__ __forceinline__ void split2(float a, float b, uint32_t& hi, uint32_t& lo) {
    __nv_bfloat16 ah = __float2bfloat16(a);
    __nv_bfloat16 bh = __float2bfloat16(b);
    __nv_bfloat16 al = __float2bfloat16(a - __bfloat162float(ah));
    __nv_bfloat16 bl = __float2bfloat16(b - __bfloat162float(bh));
    hi = ((uint32_t)__bfloat16_as_ushort(bh) << 16) | __bfloat16_as_ushort(ah);
    lo = ((uint32_t)__bfloat16_as_ushort(bl) << 16) | __bfloat16_as_ushort(al);
}

// ---------------- mma.sync m16n8k16 bf16 ----------------
__device__ __forceinline__ void mma16816(float* c, const uint32_t* a, const uint32_t* b) {
    asm volatile(
        "mma.sync.aligned.m16n8k16.row.col.f32.bf16.bf16.f32 "
        "{%0,%1,%2,%3}, {%4,%5,%6,%7}, {%8,%9}, {%0,%1,%2,%3};"
        : "+f"(c[0]), "+f"(c[1]), "+f"(c[2]), "+f"(c[3])
        : "r"(a[0]), "r"(a[1]), "r"(a[2]), "r"(a[3]), "r"(b[0]), "r"(b[1]));
}

// A-fragment: rows (base+g, base+g+8), k-pairs (2tq, 2tq+8) from 144B-stride region
__device__ __forceinline__ void ldA(uint32_t* a, const unsigned char* base,
                                    int row, int ks, int g, int tq) {
    const unsigned char* p = base + (row + g) * 144 + ks * 32 + tq * 4;
    a[0] = *(const uint32_t*)(p);
    a[1] = *(const uint32_t*)(p + 8 * 144);
    a[2] = *(const uint32_t*)(p + 16);
    a[3] = *(const uint32_t*)(p + 8 * 144 + 16);
}
// B-fragment: n = nbase+g, k-pairs (2tq, 2tq+8) from [64n][72k] tile (144B rows)
__device__ __forceinline__ void ldB(uint32_t* b, const unsigned char* tile,
                                    int nbase, int ks, int g, int tq) {
    const unsigned char* p = tile + (nbase + g) * 144 + ks * 32 + tq * 4;
    b[0] = *(const uint32_t*)(p);
    b[1] = *(const uint32_t*)(p + 16);
}

// ---------------- weight scratch: pre-split bf16 hi/lo padded tiles ----------------
// tile = [64 n][72 k] bf16 = 9216 B (pad cols 64..71 never read)
// per stream, 20 tiles:
//   0-3  fc1 hi (kc=0..3)     4-7  fc1 lo
//   8-10 wih hi (r,z,n)      11-13 wih lo
//  14-16 whh hi (r,z,n)      17-19 whh lo
#define TILE_H 4608          // halfs per tile
#define TILE_B 9216          // bytes per tile
__device__ __align__(16) __nv_bfloat16 g_wt[2][20][TILE_H];

__global__ void convert_weights_kernel(
    const float* __restrict__ fc1a, const float* __restrict__ wiha, const float* __restrict__ whha,
    const float* __restrict__ fc1b, const float* __restrict__ wihb, const float* __restrict__ whhb)
{
    int tid = blockIdx.x * blockDim.x + threadIdx.x;
    int stride = gridDim.x * blockDim.x;
    for (int s = 0; s < 2; ++s) {
        const float* fc1 = s ? fc1b : fc1a;
        const float* wih = s ? wihb : wiha;
        const float* whh = s ? whhb : whha;
        for (int e = tid; e < 40960; e += stride) {
            float v; int th, tl; uint32_t off;
            if (e < 16384) {                        // fc1 [64,256]
                int n = e >> 8, k = e & 255, kc = k >> 6, kk = k & 63;
                v = fc1[e]; th = kc; tl = 4 + kc; off = n * 72 + kk;
            } else if (e < 28672) {                 // wih [192,64]
                int e2 = e - 16384, j = e2 >> 6, k = e2 & 63, gg = j >> 6, n = j & 63;
                v = wih[e2]; th = 8 + gg; tl = 11 + gg; off = n * 72 + k;
            } else {                                // whh [192,64]
                int e2 = e - 28672, j = e2 >> 6, k = e2 & 63, gg = j >> 6, n = j & 63;
                v = whh[e2]; th = 14 + gg; tl = 17 + gg; off = n * 72 + k;
            }
            __nv_bfloat16 hi = __float2bfloat16(v);
            __nv_bfloat16 lo = __float2bfloat16(v - __bfloat162float(hi));
            g_wt[s][th][off] = hi;
            g_wt[s][tl][off] = lo;
        }
    }
}

// ---------------- smem layout (bytes) ----------------
#define SM_W    0                 // 12 tile slots max = 110592
#define SM_XHI  110592            // [128][72 bf16] = 18432
#define SM_XLO  129024
#define SM_HHI  147456
#define SM_HLO  165888
#define SM_HST  184320            // float [128][65] = 33280
#define SM_BIH  217600            // float[192]
#define SM_BHH  218368            // float[192]
#define SM_B1   219136            // float[64]
#define SM_W2   219392            // float[64]
#define SMEM_TOTAL 219648

__global__ __launch_bounds__(NT, 1)
void gru_hmma_kernel(
    const float* __restrict__ obs, const float* __restrict__ h1, const float* __restrict__ h2,
    const int* __restrict__ mask,
    const float* __restrict__ bih1, const float* __restrict__ bhh1,
    const float* __restrict__ bfc1_1, const float* __restrict__ wfc2_1, const float* __restrict__ bfc2_1,
    const float* __restrict__ bih2, const float* __restrict__ bhh2,
    const float* __restrict__ bfc1_2, const float* __restrict__ wfc2_2, const float* __restrict__ bfc2_2,
    float* __restrict__ v1, float* __restrict__ v2,
    float* __restrict__ ho1, float* __restrict__ ho2)
{
    extern __shared__ __align__(16) unsigned char sm[];
    unsigned char* Wb  = sm + SM_W;
    unsigned char* XHI = sm + SM_XHI;
    unsigned char* XLO = sm + SM_XLO;
    unsigned char* HHI = sm + SM_HHI;
    unsigned char* HLO = sm + SM_HLO;
    float* HST = (float*)(sm + SM_HST);
    float* BIH = (float*)(sm + SM_BIH);
    float* BHH = (float*)(sm + SM_BHH);
    float* B1  = (float*)(sm + SM_B1);
    float* W2  = (float*)(sm + SM_W2);

    const int tid  = threadIdx.x;
    const int wid  = tid >> 5;
    const int lane = tid & 31;
    const int g    = lane >> 2;
    const int tq   = lane & 3;

    const int stream = blockIdx.x & 1;
    const int tile   = blockIdx.x >> 1;
    const int row0   = tile * 128;

    const float* hin = stream ? h2 : h1;
    const float* bih = stream ? bih2 : bih1;
    const float* bhh = stream ? bhh2 : bhh1;
    const float* bf1 = stream ? bfc1_2 : bfc1_1;
    const float* wf2 = stream ? wfc2_2 : wfc2_1;
    const float* bf2 = stream ? bfc2_2 : bfc2_1;
    float* vout = stream ? v2 : v1;
    float* hout = stream ? ho2 : ho1;

    // ---- Phase A: fc1 weights, biases, H ----
    {
        const int4* src = (const int4*)&g_wt[stream][0][0];   // tiles 0..7
        int4* dst = (int4*)Wb;
        for (int i = tid; i < (8 * TILE_B) / 16; i += NT) dst[i] = src[i];
    }
    for (int i = tid; i < 192; i += NT) { BIH[i] = bih[i]; BHH[i] = bhh[i]; }
    if (tid < 64) { B1[tid] = bf1[tid]; W2[tid] = wf2[tid]; }
#pragma unroll
    for (int it = 0; it < 8; ++it) {
        int idx4 = tid + it * NT;                 // 2048 float4s = 128x64
        int r = idx4 >> 4, c4 = idx4 & 15;
        float4 v = *(const float4*)(hin + (size_t)(row0 + r) * 64 + 4 * c4);
        float* hd = HST + r * 65 + 4 * c4;
        hd[0] = v.x; hd[1] = v.y; hd[2] = v.z; hd[3] = v.w;
        uint32_t hi01, lo01, hi23, lo23;
        split2(v.x, v.y, hi01, lo01);
        split2(v.z, v.w, hi23, lo23);
        uint32_t off = (uint32_t)(r * 144 + c4 * 8);
        *(uint32_t*)(HHI + off)     = hi01;  *(uint32_t*)(HHI + off + 4) = hi23;
        *(uint32_t*)(HLO + off)     = lo01;  *(uint32_t*)(HLO + off + 4) = lo23;
    }
    __syncthreads();

    const int rbase = 16 * wid;     // warp's 16-row strip
    const int rowa  = rbase + g;
    const int rowb  = rowa + 8;

    // ---- Phase B: fc1 GEMM, K=256 in 4 chunks of 64, 3-term bf16 split ----
    float acc1[8][4];
#pragma unroll
    for (int f = 0; f < 8; ++f)
#pragma unroll
        for (int e = 0; e < 4; ++e) acc1[f][e] = 0.0f;

    for (int kc = 0; kc < 4; ++kc) {
        if (kc) __syncthreads();     // all warps done reading prev obs chunk
#pragma unroll
        for (int it = 0; it < 8; ++it) {
            int idx4 = tid + it * NT;
            int r = idx4 >> 4, c4 = idx4 & 15;
            float4 v = *(const float4*)(obs + (size_t)(row0 + r) * 256 + kc * 64 + 4 * c4);
            uint32_t hi01, lo01, hi23, lo23;
            split2(v.x, v.y, hi01, lo01);
            split2(v.z, v.w, hi23, lo23);
            uint32_t off = (uint32_t)(r * 144 + c4 * 8);
            *(uint32_t*)(XHI + off)     = hi01;  *(uint32_t*)(XHI + off + 4) = hi23;
            *(uint32_t*)(XLO + off)     = lo01;  *(uint32_t*)(XLO + off + 4) = lo23;
        }
        __syncthreads();
#pragma unroll
        for (int t = 0; t < 3; ++t) {
            const unsigned char* Ab = (t == 2) ? XLO : XHI;
            const unsigned char* Bt = Wb + ((t == 1) ? (4 + kc) : kc) * TILE_B;
#pragma unroll
            for (int ks = 0; ks < 4; ++ks) {
                uint32_t a[4];
                ldA(a, Ab, rbase, ks, g, tq);
#pragma unroll
                for (int f = 0; f < 8; ++f) {
                    uint32_t b[2];
                    ldB(b, Bt, 8 * f, ks, g, tq);
                    mma16816(acc1[f], a, b);
                }
            }
        }
    }
    __syncthreads();   // fc1 mma done everywhere; safe to overwrite ACT + W

    // ---- Phase C: X = tanh(acc+b) -> smem (hi/lo), swap in gate weights ----
#pragma unroll
    for (int f = 0; f < 8; ++f) {
        int col = 8 * f + 2 * tq;
        float x0 = ftanh(acc1[f][0] + B1[col]);
        float x1 = ftanh(acc1[f][1] + B1[col + 1]);
        float x2 = ftanh(acc1[f][2] + B1[col]);
        float x3 = ftanh(acc1[f][3] + B1[col + 1]);
        uint32_t hi01, lo01, hi23, lo23;
        split2(x0, x1, hi01, lo01);
        split2(x2, x3, hi23, lo23);
        uint32_t offa = (uint32_t)(rowa * 144 + col * 2);
        uint32_t offb = (uint32_t)(rowb * 144 + col * 2);
        *(uint32_t*)(XHI + offa) = hi01;  *(uint32_t*)(XLO + offa) = lo01;
        *(uint32_t*)(XHI + offb) = hi23;  *(uint32_t*)(XLO + offb) = lo23;
    }
    {
        const int4* src = (const int4*)&g_wt[stream][8][0];   // tiles 8..19
        int4* dst = (int4*)Wb;
        for (int i = tid; i < (12 * TILE_B) / 16; i += NT) dst[i] = src[i];
    }
    __syncthreads();

    // ---- Phase E: GRU gate GEMMs + fused epilogue, two N=32 halves ----
    float vr0 = 0.0f, vr1 = 0.0f;
    const int ma = mask[row0 + rowa];
    const int mb = mask[row0 + rowb];
    const float b2 = bf2[0];

#pragma unroll
    for (int half = 0; half < 2; ++half) {
        float ar[4][4], az[4][4], ani[4][4], anh[4][4];
#pragma unroll
        for (int f = 0; f < 4; ++f)
#pragma unroll
            for (int e = 0; e < 4; ++e) { ar[f][e] = az[f][e] = ani[f][e] = anh[f][e] = 0.0f; }

#pragma unroll
        for (int ks = 0; ks < 4; ++ks) {
            uint32_t axh[4], axl[4], ahh[4], ahl[4];
            ldA(axh, XHI, rbase, ks, g, tq);
            ldA(axl, XLO, rbase, ks, g, tq);
            ldA(ahh, HHI, rbase, ks, g, tq);
            ldA(ahl, HLO, rbase, ks, g, tq);
#pragma unroll
            for (int f = 0; f < 4; ++f) {
                int nb = half * 32 + 8 * f;
                uint32_t bs[12][2];
#pragma unroll
                for (int s = 0; s < 12; ++s) ldB(bs[s], Wb + s * TILE_B, nb, ks, g, tq);
                // r: X(wih_r hi,lo) + H(whh_r hi,lo), merged accumulator
                mma16816(ar[f], axh, bs[0]);  mma16816(ar[f], axh, bs[3]);  mma16816(ar[f], axl, bs[0]);
                mma16816(ar[f], ahh, bs[6]);  mma16816(ar[f], ahh, bs[9]);  mma16816(ar[f], ahl, bs[6]);
                // z
                mma16816(az[f], axh, bs[1]);  mma16816(az[f], axh, bs[4]);  mma16816(az[f], axl, bs[1]);
                mma16816(az[f], ahh, bs[7]);  mma16816(az[f], ahh, bs[10]); mma16816(az[f], ahl, bs[7]);
                // n input part
                mma16816(ani[f], axh, bs[2]); mma16816(ani[f], axh, bs[5]); mma16816(ani[f], axl, bs[2]);
                // n hidden part
                mma16816(anh[f], ahh, bs[8]); mma16816(anh[f], ahh, bs[11]); mma16816(anh[f], ahl, bs[8]);
            }
        }

        // epilogue for this half
#pragma unroll
        for (int f = 0; f < 4; ++f) {
#pragma unroll
            for (int e = 0; e < 4; ++e) {
                int c   = half * 32 + 8 * f + 2 * tq + (e & 1);
                int row = (e < 2) ? rowa : rowb;
                int m   = (e < 2) ? ma : mb;
                float rr = fsigm(ar[f][e] + BIH[c] + BHH[c]);
                float zz = fsigm(az[f][e] + BIH[64 + c] + BHH[64 + c]);
                float nn = ftanh(ani[f][e] + BIH[128 + c] + rr * (anh[f][e] + BHH[128 + c]));
                float hold = HST[row * 65 + c];
                float hg = (1.0f - zz) * nn + zz * hold;
                float hn = m ? hg : hold;
                HST[row * 65 + c] = hn;
                float vterm = hn * W2[c];
                if (e < 2) vr0 += vterm; else vr1 += vterm;
            }
        }
    }

    // value head reduce across the quad (lanes 4g+tq, tq=0..3)
#pragma unroll
    for (int off = 1; off <= 2; off <<= 1) {
        vr0 += __shfl_xor_sync(0xffffffffu, vr0, off);
        vr1 += __shfl_xor_sync(0xffffffffu, vr1, off);
    }
    if (tq == 0) {
        vout[row0 + rowa] = vr0 + b2;
        vout[row0 + rowb] = vr1 + b2;
    }

    __syncthreads();
    // coalesced new_h store
#pragma unroll
    for (int it = 0; it < 32; ++it) {
        int i = tid + it * NT;           // 8192
        int r = i >> 6, c = i & 63;
        hout[(size_t)(row0 + r) * 64 + c] = HST[r * 65 + c];
    }
}

// ---------------- launch ----------------
extern "C" void kernel_launch(void* const* d_in, const int* in_sizes, int n_in,
                              void* d_out, int out_size) {
    const float* obs = (const float*)d_in[0];
    const float* h1  = (const float*)d_in[1];
    const float* h2  = (const float*)d_in[2];
    const int*   msk = (const int*)d_in[3];

    const int B = in_sizes[1] / 64;   // 262144

    float* out = (float*)d_out;
    float* v1  = out;
    float* v2  = out + (size_t)B;
    float* ho1 = out + 2 * (size_t)B;
    float* ho2 = ho1 + (size_t)B * 64;

    convert_weights_kernel<<<160, 256>>>(
        (const float*)d_in[4],  (const float*)d_in[6],  (const float*)d_in[7],
        (const float*)d_in[12], (const float*)d_in[14], (const float*)d_in[15]);

    cudaFuncSetAttribute(gru_hmma_kernel,
                         cudaFuncAttributeMaxDynamicSharedMemorySize, SMEM_TOTAL);

    dim3 grid((B / 128) * 2);
    gru_hmma_kernel<<<grid, NT, SMEM_TOTAL>>>(
        obs, h1, h2, msk,
        (const float*)d_in[8],  (const float*)d_in[9],
        (const float*)d_in[5],  (const float*)d_in[10], (const float*)d_in[11],
        (const float*)d_in[16], (const float*)d_in[17],
        (const float*)d_in[13], (const float*)d_in[18], (const float*)d_in[19],
        v1, v2, ho1, ho2);
}

// round 5
// speedup vs baseline: 3.9218x; 1.0906x over previous
#include <cuda_runtime.h>
#include <cuda_bf16.h>
#include <stdint.h>

#define NT 512

// ---------------- math helpers ----------------
__device__ __forceinline__ float fsigm(float x) { return __fdividef(1.0f, 1.0f + __expf(-x)); }
__device__ __forceinline__ float ftanh(float x) {
    return 1.0f - __fdividef(2.0f, __expf(2.0f * x) + 1.0f);
}
__device__ __forceinline__ void split2(float a, float b, uint32_t& hi, uint32_t& lo) {
    __nv_bfloat16 ah = __float2bfloat16(a);
    __nv_bfloat16 bh = __float2bfloat16(b);
    __nv_bfloat16 al = __float2bfloat16(a - __bfloat162float(ah));
    __nv_bfloat16 bl = __float2bfloat16(b - __bfloat162float(bh));
    hi = ((uint32_t)__bfloat16_as_ushort(bh) << 16) | __bfloat16_as_ushort(ah);
    lo = ((uint32_t)__bfloat16_as_ushort(bl) << 16) | __bfloat16_as_ushort(al);
}

// ---------------- mma.sync m16n8k16 bf16 ----------------
__device__ __forceinline__ void mma16816(float* c, const uint32_t* a, const uint32_t* b) {
    asm volatile(
        "mma.sync.aligned.m16n8k16.row.col.f32.bf16.bf16.f32 "
        "{%0,%1,%2,%3}, {%4,%5,%6,%7}, {%8,%9}, {%0,%1,%2,%3};"
        : "+f"(c[0]), "+f"(c[1]), "+f"(c[2]), "+f"(c[3])
        : "r"(a[0]), "r"(a[1]), "r"(a[2]), "r"(a[3]), "r"(b[0]), "r"(b[1]));
}
// A-frag: rows (rbase+g, +8), k-pairs (2tq, 2tq+8); 144B row stride
__device__ __forceinline__ void ldA(uint32_t* a, const unsigned char* base,
                                    int rbase, int ks, int g, int tq) {
    const unsigned char* p = base + (rbase + g) * 144 + ks * 32 + tq * 4;
    a[0] = *(const uint32_t*)(p);
    a[1] = *(const uint32_t*)(p + 8 * 144);
    a[2] = *(const uint32_t*)(p + 16);
    a[3] = *(const uint32_t*)(p + 8 * 144 + 16);
}
// B-frag: n = nbase+g; [64n][72k] tile, 144B rows
__device__ __forceinline__ void ldB(uint32_t* b, const unsigned char* tile,
                                    int nbase, int ks, int g, int tq) {
    const unsigned char* p = tile + (nbase + g) * 144 + ks * 32 + tq * 4;
    b[0] = *(const uint32_t*)(p);
    b[1] = *(const uint32_t*)(p + 16);
}

// ---------------- weight scratch (pre-split bf16 hi/lo, padded [64][72]) -------
#define TILE_H 4608
#define TILE_B 9216
__device__ __align__(16) __nv_bfloat16 g_wt[2][20][TILE_H];

__global__ void convert_weights_kernel(
    const float* __restrict__ fc1a, const float* __restrict__ wiha, const float* __restrict__ whha,
    const float* __restrict__ fc1b, const float* __restrict__ wihb, const float* __restrict__ whhb)
{
    int tid = blockIdx.x * blockDim.x + threadIdx.x;
    int stride = gridDim.x * blockDim.x;
    for (int s = 0; s < 2; ++s) {
        const float* fc1 = s ? fc1b : fc1a;
        const float* wih = s ? wihb : wiha;
        const float* whh = s ? whhb : whha;
        for (int e = tid; e < 40960; e += stride) {
            float v; int th, tl; uint32_t off;
            if (e < 16384) {                        // fc1 [64,256] -> tiles 0..7
                int n = e >> 8, k = e & 255, kc = k >> 6, kk = k & 63;
                v = fc1[e]; th = kc; tl = 4 + kc; off = n * 72 + kk;
            } else if (e < 28672) {                 // wih [192,64] -> tiles 8..13
                int e2 = e - 16384, j = e2 >> 6, k = e2 & 63, gg = j >> 6, n = j & 63;
                v = wih[e2]; th = 8 + gg; tl = 11 + gg; off = n * 72 + k;
            } else {                                // whh [192,64] -> tiles 14..19
                int e2 = e - 28672, j = e2 >> 6, k = e2 & 63, gg = j >> 6, n = j & 63;
                v = whh[e2]; th = 14 + gg; tl = 17 + gg; off = n * 72 + k;
            }
            __nv_bfloat16 hi = __float2bfloat16(v);
            __nv_bfloat16 lo = __float2bfloat16(v - __bfloat162float(hi));
            g_wt[s][th][off] = hi;
            g_wt[s][tl][off] = lo;
        }
    }
}

// ---------------- smem layout (bytes) ----------------
#define SM_W    0                 // 12 tiles = 110592
#define SM_XHI  110592
#define SM_XLO  129024
#define SM_HHI  147456
#define SM_HLO  165888
#define SM_HSN  184320            // fp32 new_h stage [128][65] = 33280
#define SM_BIH  217600            // float[192]
#define SM_BHH  218368
#define SM_B1   219136
#define SM_W2   219392
#define SM_VP   219648            // float[128][2]
#define SMEM_TOTAL 220672

__global__ __launch_bounds__(NT, 1)
void gru_hmma_kernel(
    const float* __restrict__ obs, const float* __restrict__ h1, const float* __restrict__ h2,
    const int* __restrict__ mask,
    const float* __restrict__ bih1, const float* __restrict__ bhh1,
    const float* __restrict__ bfc1_1, const float* __restrict__ wfc2_1, const float* __restrict__ bfc2_1,
    const float* __restrict__ bih2, const float* __restrict__ bhh2,
    const float* __restrict__ bfc1_2, const float* __restrict__ wfc2_2, const float* __restrict__ bfc2_2,
    float* __restrict__ v1, float* __restrict__ v2,
    float* __restrict__ ho1, float* __restrict__ ho2)
{
    extern __shared__ __align__(16) unsigned char sm[];
    unsigned char* Wb  = sm + SM_W;
    unsigned char* XHI = sm + SM_XHI;
    unsigned char* XLO = sm + SM_XLO;
    unsigned char* HHI = sm + SM_HHI;
    unsigned char* HLO = sm + SM_HLO;
    float* HSN = (float*)(sm + SM_HSN);
    float* BIH = (float*)(sm + SM_BIH);
    float* BHH = (float*)(sm + SM_BHH);
    float* B1  = (float*)(sm + SM_B1);
    float* W2  = (float*)(sm + SM_W2);
    float* VP  = (float*)(sm + SM_VP);

    const int tid  = threadIdx.x;
    const int wid  = tid >> 5;
    const int lane = tid & 31;
    const int g    = lane >> 2;
    const int tq   = lane & 3;

    const int strip = wid & 7;          // 16-row strip
    const int nhalf = wid >> 3;         // N half (0: cols 0-31, 1: cols 32-63)
    const int rbase = 16 * strip;
    const int rowa  = rbase + g;
    const int rowb  = rowa + 8;
    const int nb0   = 32 * nhalf;

    const int stream = blockIdx.x & 1;
    const int row0   = (blockIdx.x >> 1) * 128;

    const float* hin = stream ? h2 : h1;
    const float* bih = stream ? bih2 : bih1;
    const float* bhh = stream ? bhh2 : bhh1;
    const float* bf1 = stream ? bfc1_2 : bfc1_1;
    const float* wf2 = stream ? wfc2_2 : wfc2_1;
    const float* bf2 = stream ? bfc2_2 : bfc2_1;
    float* vout = stream ? v2 : v1;
    float* hout = stream ? ho2 : ho1;

    // ---- Phase A: fc1 weights (tiles 0..7), biases, H planes ----
    {
        const int4* src = (const int4*)&g_wt[stream][0][0];
        int4* dst = (int4*)Wb;
        for (int i = tid; i < (8 * TILE_B) / 16; i += NT) dst[i] = src[i];
    }
    for (int i = tid; i < 192; i += NT) { BIH[i] = bih[i]; BHH[i] = bhh[i]; }
    if (tid < 64) { B1[tid] = bf1[tid]; W2[tid] = wf2[tid]; }
#pragma unroll
    for (int it = 0; it < 4; ++it) {
        int idx4 = tid + it * NT;                // 2048 float4s = 128x64
        int r = idx4 >> 4, c4 = idx4 & 15;
        float4 v = *(const float4*)(hin + (size_t)(row0 + r) * 64 + 4 * c4);
        uint32_t hi01, lo01, hi23, lo23;
        split2(v.x, v.y, hi01, lo01);
        split2(v.z, v.w, hi23, lo23);
        uint32_t off = (uint32_t)(r * 144 + c4 * 8);
        *(uint32_t*)(HHI + off)     = hi01;  *(uint32_t*)(HHI + off + 4) = hi23;
        *(uint32_t*)(HLO + off)     = lo01;  *(uint32_t*)(HLO + off + 4) = lo23;
    }
    __syncthreads();

    // ---- Phase B: fc1 GEMM (K=256, 4 chunks), 3-term bf16 split ----
    float acc1[4][4];
#pragma unroll
    for (int f = 0; f < 4; ++f)
#pragma unroll
        for (int e = 0; e < 4; ++e) acc1[f][e] = 0.0f;

    for (int kc = 0; kc < 4; ++kc) {
        if (kc) __syncthreads();
#pragma unroll
        for (int it = 0; it < 4; ++it) {
            int idx4 = tid + it * NT;
            int r = idx4 >> 4, c4 = idx4 & 15;
            float4 v = *(const float4*)(obs + (size_t)(row0 + r) * 256 + kc * 64 + 4 * c4);
            uint32_t hi01, lo01, hi23, lo23;
            split2(v.x, v.y, hi01, lo01);
            split2(v.z, v.w, hi23, lo23);
            uint32_t off = (uint32_t)(r * 144 + c4 * 8);
            *(uint32_t*)(XHI + off)     = hi01;  *(uint32_t*)(XHI + off + 4) = hi23;
            *(uint32_t*)(XLO + off)     = lo01;  *(uint32_t*)(XLO + off + 4) = lo23;
        }
        __syncthreads();
#pragma unroll
        for (int t = 0; t < 3; ++t) {
            const unsigned char* Ab = (t == 2) ? XLO : XHI;
            const unsigned char* Bt = Wb + ((t == 1) ? (4 + kc) : kc) * TILE_B;
#pragma unroll
            for (int ks = 0; ks < 4; ++ks) {
                uint32_t a[4];
                ldA(a, Ab, rbase, ks, g, tq);
#pragma unroll
                for (int f = 0; f < 4; ++f) {
                    uint32_t b[2];
                    ldB(b, Bt, nb0 + 8 * f, ks, g, tq);
                    mma16816(acc1[f], a, b);
                }
            }
        }
    }
    __syncthreads();   // all fc1 mma reads done; X planes and W reusable

    // ---- Phase C: X = tanh(acc+b) -> X planes; swap in gate weights ----
#pragma unroll
    for (int f = 0; f < 4; ++f) {
        int col = nb0 + 8 * f + 2 * tq;
        float x0 = ftanh(acc1[f][0] + B1[col]);
        float x1 = ftanh(acc1[f][1] + B1[col + 1]);
        float x2 = ftanh(acc1[f][2] + B1[col]);
        float x3 = ftanh(acc1[f][3] + B1[col + 1]);
        uint32_t hi01, lo01, hi23, lo23;
        split2(x0, x1, hi01, lo01);
        split2(x2, x3, hi23, lo23);
        uint32_t offa = (uint32_t)(rowa * 144 + col * 2);
        uint32_t offb = (uint32_t)(rowb * 144 + col * 2);
        *(uint32_t*)(XHI + offa) = hi01;  *(uint32_t*)(XLO + offa) = lo01;
        *(uint32_t*)(XHI + offb) = hi23;  *(uint32_t*)(XLO + offb) = lo23;
    }
    {
        const int4* src = (const int4*)&g_wt[stream][8][0];   // tiles 8..19
        int4* dst = (int4*)Wb;
        for (int i = tid; i < (12 * TILE_B) / 16; i += NT) dst[i] = src[i];
    }
    __syncthreads();

    // ---- Phase E: GRU gate GEMMs + fused epilogue (f-pairs to bound regs) ----
    // Wb tiles: 0=ih_r_hi 1=ih_z_hi 2=ih_n_hi 3=ih_r_lo 4=ih_z_lo 5=ih_n_lo
    //           6=hh_r_hi 7=hh_z_hi 8=hh_n_hi 9=hh_r_lo 10=hh_z_lo 11=hh_n_lo
    float vr0 = 0.0f, vr1 = 0.0f;
    const int ma = mask[row0 + rowa];
    const int mb = mask[row0 + rowb];
    const __nv_bfloat16* HHIh = (const __nv_bfloat16*)HHI;
    const __nv_bfloat16* HLOh = (const __nv_bfloat16*)HLO;

#pragma unroll
    for (int fp = 0; fp < 2; ++fp) {
        float ar[2][4], az[2][4], ani[2][4], anh[2][4];
#pragma unroll
        for (int ff = 0; ff < 2; ++ff)
#pragma unroll
            for (int e = 0; e < 4; ++e) { ar[ff][e] = az[ff][e] = ani[ff][e] = anh[ff][e] = 0.0f; }

#pragma unroll
        for (int ks = 0; ks < 4; ++ks) {
            uint32_t axh[4], axl[4], ahh[4], ahl[4];
            ldA(axh, XHI, rbase, ks, g, tq);
            ldA(axl, XLO, rbase, ks, g, tq);
            ldA(ahh, HHI, rbase, ks, g, tq);
            ldA(ahl, HLO, rbase, ks, g, tq);
#pragma unroll
            for (int ff = 0; ff < 2; ++ff) {
                int nb = nb0 + 8 * (2 * fp + ff);
                uint32_t bs[12][2];
#pragma unroll
                for (int s = 0; s < 12; ++s) ldB(bs[s], Wb + s * TILE_B, nb, ks, g, tq);
                mma16816(ar[ff], axh, bs[0]);  mma16816(ar[ff], axh, bs[3]);  mma16816(ar[ff], axl, bs[0]);
                mma16816(ar[ff], ahh, bs[6]);  mma16816(ar[ff], ahh, bs[9]);  mma16816(ar[ff], ahl, bs[6]);
                mma16816(az[ff], axh, bs[1]);  mma16816(az[ff], axh, bs[4]);  mma16816(az[ff], axl, bs[1]);
                mma16816(az[ff], ahh, bs[7]);  mma16816(az[ff], ahh, bs[10]); mma16816(az[ff], ahl, bs[7]);
                mma16816(ani[ff], axh, bs[2]); mma16816(ani[ff], axh, bs[5]); mma16816(ani[ff], axl, bs[2]);
                mma16816(anh[ff], ahh, bs[8]); mma16816(anh[ff], ahh, bs[11]); mma16816(anh[ff], ahl, bs[8]);
            }
        }

        // fused epilogue for this f-pair
#pragma unroll
        for (int ff = 0; ff < 2; ++ff) {
#pragma unroll
            for (int e = 0; e < 4; ++e) {
                int c   = nb0 + 8 * (2 * fp + ff) + 2 * tq + (e & 1);
                int row = (e < 2) ? rowa : rowb;
                int m   = (e < 2) ? ma : mb;
                float rr = fsigm(ar[ff][e] + BIH[c] + BHH[c]);
                float zz = fsigm(az[ff][e] + BIH[64 + c] + BHH[64 + c]);
                float nn = ftanh(ani[ff][e] + BIH[128 + c] + rr * (anh[ff][e] + BHH[128 + c]));
                float hold = __bfloat162float(HHIh[row * 72 + c]) + __bfloat162float(HLOh[row * 72 + c]);
                float hg = (1.0f - zz) * nn + zz * hold;
                float hn = m ? hg : hold;
                HSN[row * 65 + c] = hn;
                float vterm = hn * W2[c];
                if (e < 2) vr0 += vterm; else vr1 += vterm;
            }
        }
    }

    // quad reduce (tq lanes) and stage value partials
#pragma unroll
    for (int off = 1; off <= 2; off <<= 1) {
        vr0 += __shfl_xor_sync(0xffffffffu, vr0, off);
        vr1 += __shfl_xor_sync(0xffffffffu, vr1, off);
    }
    if (tq == 0) {
        VP[rowa * 2 + nhalf] = vr0;
        VP[rowb * 2 + nhalf] = vr1;
    }
    __syncthreads();

    // ---- final stores ----
    if (tid < 128)
        vout[row0 + tid] = VP[tid * 2] + VP[tid * 2 + 1] + bf2[0];
#pragma unroll
    for (int it = 0; it < 16; ++it) {
        int i = tid + it * NT;           // 8192
        int r = i >> 6, c = i & 63;
        hout[(size_t)(row0 + r) * 64 + c] = HSN[r * 65 + c];
    }
}

// ---------------- launch ----------------
extern "C" void kernel_launch(void* const* d_in, const int* in_sizes, int n_in,
                              void* d_out, int out_size) {
    const float* obs = (const float*)d_in[0];
    const float* h1  = (const float*)d_in[1];
    const float* h2  = (const float*)d_in[2];
    const int*   msk = (const int*)d_in[3];

    const int B = in_sizes[1] / 64;   // 262144

    float* out = (float*)d_out;
    float* v1  = out;
    float* v2  = out + (size_t)B;
    float* ho1 = out + 2 * (size_t)B;
    float* ho2 = ho1 + (size_t)B * 64;

    convert_weights_kernel<<<160, 256>>>(
        (const float*)d_in[4],  (const float*)d_in[6],  (const float*)d_in[7],
        (const float*)d_in[12], (const float*)d_in[14], (const float*)d_in[15]);

    cudaFuncSetAttribute(gru_hmma_kernel,
                         cudaFuncAttributeMaxDynamicSharedMemorySize, SMEM_TOTAL);

    dim3 grid((B / 128) * 2);
    gru_hmma_kernel<<<grid, NT, SMEM_TOTAL>>>(
        obs, h1, h2, msk,
        (const float*)d_in[8],  (const float*)d_in[9],
        (const float*)d_in[5],  (const float*)d_in[10], (const float*)d_in[11],
        (const float*)d_in[16], (const float*)d_in[17],
        (const float*)d_in[13], (const float*)d_in[18], (const float*)d_in[19],
        v1, v2, ho1, ho2);
}

// round 6
// speedup vs baseline: 4.0701x; 1.0378x over previous
#include <cuda_runtime.h>
#include <cuda_bf16.h>
#include <stdint.h>

#define NT 512

// ---------------- math helpers ----------------
__device__ __forceinline__ float fsigm(float x) { return __fdividef(1.0f, 1.0f + __expf(-x)); }
__device__ __forceinline__ float ftanh(float x) {
    return 1.0f - __fdividef(2.0f, __expf(2.0f * x) + 1.0f);
}
__device__ __forceinline__ void split2(float a, float b, uint32_t& hi, uint32_t& lo) {
    __nv_bfloat16 ah = __float2bfloat16(a);
    __nv_bfloat16 bh = __float2bfloat16(b);
    __nv_bfloat16 al = __float2bfloat16(a - __bfloat162float(ah));
    __nv_bfloat16 bl = __float2bfloat16(b - __bfloat162float(bh));
    hi = ((uint32_t)__bfloat16_as_ushort(bh) << 16) | __bfloat16_as_ushort(ah);
    lo = ((uint32_t)__bfloat16_as_ushort(bl) << 16) | __bfloat16_as_ushort(al);
}
__device__ __forceinline__ uint32_t smem_u32(const void* p) {
    uint32_t a;
    asm("{ .reg .u64 t; cvta.to.shared.u64 t, %1; cvt.u32.u64 %0, t; }" : "=r"(a) : "l"(p));
    return a;
}

// ---------------- mma + ldmatrix ----------------
__device__ __forceinline__ void mma16816(float* c, const uint32_t* a, const uint32_t* b) {
    asm volatile(
        "mma.sync.aligned.m16n8k16.row.col.f32.bf16.bf16.f32 "
        "{%0,%1,%2,%3}, {%4,%5,%6,%7}, {%8,%9}, {%0,%1,%2,%3};"
        : "+f"(c[0]), "+f"(c[1]), "+f"(c[2]), "+f"(c[3])
        : "r"(a[0]), "r"(a[1]), "r"(a[2]), "r"(a[3]), "r"(b[0]), "r"(b[1]));
}
__device__ __forceinline__ void ldsm4(uint32_t* d, uint32_t addr) {
    asm volatile("ldmatrix.sync.aligned.m8n8.x4.shared.b16 {%0,%1,%2,%3}, [%4];"
                 : "=r"(d[0]), "=r"(d[1]), "=r"(d[2]), "=r"(d[3]) : "r"(addr));
}
__device__ __forceinline__ void ldsm2(uint32_t* d, uint32_t addr) {
    asm volatile("ldmatrix.sync.aligned.m8n8.x2.shared.b16 {%0,%1}, [%2];"
                 : "=r"(d[0]), "=r"(d[1]) : "r"(addr));
}

// ---------------- weight scratch (pre-split bf16 hi/lo, padded [64][72]) -------
#define TILE_H 4608
#define TILE_B 9216
__device__ __align__(16) __nv_bfloat16 g_wt[2][20][TILE_H];

__global__ void convert_weights_kernel(
    const float* __restrict__ fc1a, const float* __restrict__ wiha, const float* __restrict__ whha,
    const float* __restrict__ fc1b, const float* __restrict__ wihb, const float* __restrict__ whhb)
{
    int tid = blockIdx.x * blockDim.x + threadIdx.x;
    int stride = gridDim.x * blockDim.x;
    for (int s = 0; s < 2; ++s) {
        const float* fc1 = s ? fc1b : fc1a;
        const float* wih = s ? wihb : wiha;
        const float* whh = s ? whhb : whha;
        for (int e = tid; e < 40960; e += stride) {
            float v; int th, tl; uint32_t off;
            if (e < 16384) {                        // fc1 [64,256] -> tiles 0..7
                int n = e >> 8, k = e & 255, kc = k >> 6, kk = k & 63;
                v = fc1[e]; th = kc; tl = 4 + kc; off = n * 72 + kk;
            } else if (e < 28672) {                 // wih [192,64] -> tiles 8..13
                int e2 = e - 16384, j = e2 >> 6, k = e2 & 63, gg = j >> 6, n = j & 63;
                v = wih[e2]; th = 8 + gg; tl = 11 + gg; off = n * 72 + k;
            } else {                                // whh [192,64] -> tiles 14..19
                int e2 = e - 28672, j = e2 >> 6, k = e2 & 63, gg = j >> 6, n = j & 63;
                v = whh[e2]; th = 14 + gg; tl = 17 + gg; off = n * 72 + k;
            }
            __nv_bfloat16 hi = __float2bfloat16(v);
            __nv_bfloat16 lo = __float2bfloat16(v - __bfloat162float(hi));
            g_wt[s][th][off] = hi;
            g_wt[s][tl][off] = lo;
        }
    }
}

// ---------------- smem layout (bytes) ----------------
#define SM_W    0                 // 12 tiles = 110592
#define SM_XHI  110592
#define SM_XLO  129024
#define SM_HHI  147456
#define SM_HLO  165888
#define SM_HSN  184320            // fp32 new_h stage [128][65] = 33280
#define SM_BIH  217600            // float[192]
#define SM_BHH  218368
#define SM_B1   219136
#define SM_W2   219392
#define SM_VP   219648            // float[128][4] = 2048
#define SMEM_TOTAL 221696

__global__ __launch_bounds__(NT, 1)
void gru_hmma_kernel(
    const float* __restrict__ obs, const float* __restrict__ h1, const float* __restrict__ h2,
    const int* __restrict__ mask,
    const float* __restrict__ bih1, const float* __restrict__ bhh1,
    const float* __restrict__ bfc1_1, const float* __restrict__ wfc2_1, const float* __restrict__ bfc2_1,
    const float* __restrict__ bih2, const float* __restrict__ bhh2,
    const float* __restrict__ bfc1_2, const float* __restrict__ wfc2_2, const float* __restrict__ bfc2_2,
    float* __restrict__ v1, float* __restrict__ v2,
    float* __restrict__ ho1, float* __restrict__ ho2)
{
    extern __shared__ __align__(16) unsigned char sm[];
    unsigned char* Wb  = sm + SM_W;
    unsigned char* XHI = sm + SM_XHI;
    unsigned char* XLO = sm + SM_XLO;
    unsigned char* HHI = sm + SM_HHI;
    unsigned char* HLO = sm + SM_HLO;
    float* HSN = (float*)(sm + SM_HSN);
    float* BIH = (float*)(sm + SM_BIH);
    float* BHH = (float*)(sm + SM_BHH);
    float* B1  = (float*)(sm + SM_B1);
    float* W2  = (float*)(sm + SM_W2);
    float* VP  = (float*)(sm + SM_VP);

    const int tid  = threadIdx.x;
    const int wid  = tid >> 5;
    const int lane = tid & 31;
    const int g    = lane >> 2;
    const int tq   = lane & 3;

    const int ms  = wid & 3;            // row quarter: rows 32ms..32ms+31
    const int nq  = wid >> 2;           // col quarter: cols 16nq..16nq+15
    const int rbase = 32 * ms;
    const int nb0   = 16 * nq;

    // ldmatrix per-lane offsets (144B row stride)
    const uint32_t aoff = (uint32_t)(((lane & 7) + ((lane >> 3) & 1) * 8) * 144 + (lane >> 4) * 16);
    const uint32_t boff = (uint32_t)((lane & 7) * 144 + ((lane >> 3) & 1) * 16);

    const uint32_t smb  = smem_u32(sm);
    const uint32_t Wu   = smb + SM_W;
    const uint32_t XHIu = smb + SM_XHI;
    const uint32_t XLOu = smb + SM_XLO;
    const uint32_t HHIu = smb + SM_HHI;
    const uint32_t HLOu = smb + SM_HLO;

    const int stream = blockIdx.x & 1;
    const int row0   = (blockIdx.x >> 1) * 128;

    const float* hin = stream ? h2 : h1;
    const float* bih = stream ? bih2 : bih1;
    const float* bhh = stream ? bhh2 : bhh1;
    const float* bf1 = stream ? bfc1_2 : bfc1_1;
    const float* wf2 = stream ? wfc2_2 : wfc2_1;
    const float* bf2 = stream ? bfc2_2 : bfc2_1;
    float* vout = stream ? v2 : v1;
    float* hout = stream ? ho2 : ho1;

    // ---- Phase A: fc1 weights (tiles 0..7), biases, H planes ----
    {
        const int4* src = (const int4*)&g_wt[stream][0][0];
        int4* dst = (int4*)Wb;
        for (int i = tid; i < (8 * TILE_B) / 16; i += NT) dst[i] = src[i];
    }
    for (int i = tid; i < 192; i += NT) { BIH[i] = bih[i]; BHH[i] = bhh[i]; }
    if (tid < 64) { B1[tid] = bf1[tid]; W2[tid] = wf2[tid]; }
#pragma unroll
    for (int it = 0; it < 4; ++it) {
        int idx4 = tid + it * NT;                // 2048 float4s = 128x64
        int r = idx4 >> 4, c4 = idx4 & 15;
        float4 v = *(const float4*)(hin + (size_t)(row0 + r) * 64 + 4 * c4);
        uint32_t hi01, lo01, hi23, lo23;
        split2(v.x, v.y, hi01, lo01);
        split2(v.z, v.w, hi23, lo23);
        uint32_t off = (uint32_t)(r * 144 + c4 * 8);
        *(uint32_t*)(HHI + off)     = hi01;  *(uint32_t*)(HHI + off + 4) = hi23;
        *(uint32_t*)(HLO + off)     = lo01;  *(uint32_t*)(HLO + off + 4) = lo23;
    }
    __syncthreads();

    // ---- Phase B: fc1 GEMM (K=256, 4 chunks), 3-term bf16 split ----
    float acc1[2][2][4];
#pragma unroll
    for (int st = 0; st < 2; ++st)
#pragma unroll
        for (int ng = 0; ng < 2; ++ng)
#pragma unroll
            for (int e = 0; e < 4; ++e) acc1[st][ng][e] = 0.0f;

    for (int kc = 0; kc < 4; ++kc) {
        if (kc) __syncthreads();
#pragma unroll
        for (int it = 0; it < 4; ++it) {
            int idx4 = tid + it * NT;
            int r = idx4 >> 4, c4 = idx4 & 15;
            float4 v = *(const float4*)(obs + (size_t)(row0 + r) * 256 + kc * 64 + 4 * c4);
            uint32_t hi01, lo01, hi23, lo23;
            split2(v.x, v.y, hi01, lo01);
            split2(v.z, v.w, hi23, lo23);
            uint32_t off = (uint32_t)(r * 144 + c4 * 8);
            *(uint32_t*)(XHI + off)     = hi01;  *(uint32_t*)(XHI + off + 4) = hi23;
            *(uint32_t*)(XLO + off)     = lo01;  *(uint32_t*)(XLO + off + 4) = lo23;
        }
        __syncthreads();
        const uint32_t bth = Wu + (uint32_t)kc * TILE_B;
        const uint32_t btl = Wu + (uint32_t)(4 + kc) * TILE_B;
#pragma unroll 1
        for (int ks = 0; ks < 4; ++ks) {
            uint32_t xh[2][4], xl[2][4];
#pragma unroll
            for (int st = 0; st < 2; ++st) {
                uint32_t ro = (uint32_t)((rbase + 16 * st) * 144 + ks * 32) + aoff;
                ldsm4(xh[st], XHIu + ro);
                ldsm4(xl[st], XLOu + ro);
            }
#pragma unroll
            for (int ng = 0; ng < 2; ++ng) {
                uint32_t no = (uint32_t)((nb0 + 8 * ng) * 144 + ks * 32) + boff;
                uint32_t bh[2], bl[2];
                ldsm2(bh, bth + no);
                ldsm2(bl, btl + no);
                mma16816(acc1[0][ng], xh[0], bh);  mma16816(acc1[1][ng], xh[1], bh);
                mma16816(acc1[0][ng], xh[0], bl);  mma16816(acc1[1][ng], xh[1], bl);
                mma16816(acc1[0][ng], xl[0], bh);  mma16816(acc1[1][ng], xl[1], bh);
            }
        }
    }
    __syncthreads();   // fc1 mma reads done; X planes and W reusable

    // ---- Phase C: X = tanh(acc+b) -> X planes; swap in gate weights ----
#pragma unroll
    for (int st = 0; st < 2; ++st)
#pragma unroll
        for (int ng = 0; ng < 2; ++ng) {
            int col = nb0 + 8 * ng + 2 * tq;
            int ra = rbase + 16 * st + g;
            int rb = ra + 8;
            float x0 = ftanh(acc1[st][ng][0] + B1[col]);
            float x1 = ftanh(acc1[st][ng][1] + B1[col + 1]);
            float x2 = ftanh(acc1[st][ng][2] + B1[col]);
            float x3 = ftanh(acc1[st][ng][3] + B1[col + 1]);
            uint32_t hi01, lo01, hi23, lo23;
            split2(x0, x1, hi01, lo01);
            split2(x2, x3, hi23, lo23);
            uint32_t offa = (uint32_t)(ra * 144 + col * 2);
            uint32_t offb = (uint32_t)(rb * 144 + col * 2);
            *(uint32_t*)(XHI + offa) = hi01;  *(uint32_t*)(XLO + offa) = lo01;
            *(uint32_t*)(XHI + offb) = hi23;  *(uint32_t*)(XLO + offb) = lo23;
        }
    {
        const int4* src = (const int4*)&g_wt[stream][8][0];   // tiles 8..19 -> slots 0..11
        int4* dst = (int4*)Wb;
        for (int i = tid; i < (12 * TILE_B) / 16; i += NT) dst[i] = src[i];
    }
    __syncthreads();

    // ---- Phase E: GRU gate GEMMs ----
    // slots: 0=ih_r_hi 1=ih_z_hi 2=ih_n_hi 3=ih_r_lo 4=ih_z_lo 5=ih_n_lo
    //        6=hh_r_hi 7=hh_z_hi 8=hh_n_hi 9=hh_r_lo 10=hh_z_lo 11=hh_n_lo
    float ar[2][2][4], az[2][2][4], ani[2][2][4], anh[2][2][4];
#pragma unroll
    for (int st = 0; st < 2; ++st)
#pragma unroll
        for (int ng = 0; ng < 2; ++ng)
#pragma unroll
            for (int e = 0; e < 4; ++e) {
                ar[st][ng][e] = az[st][ng][e] = ani[st][ng][e] = anh[st][ng][e] = 0.0f;
            }

#pragma unroll 1
    for (int ks = 0; ks < 4; ++ks) {
        uint32_t axh[2][4], axl[2][4], ahh[2][4], ahl[2][4];
#pragma unroll
        for (int st = 0; st < 2; ++st) {
            uint32_t ro = (uint32_t)((rbase + 16 * st) * 144 + ks * 32) + aoff;
            ldsm4(axh[st], XHIu + ro);
            ldsm4(axl[st], XLOu + ro);
            ldsm4(ahh[st], HHIu + ro);
            ldsm4(ahl[st], HLOu + ro);
        }
#pragma unroll
        for (int ng = 0; ng < 2; ++ng) {
            uint32_t no = (uint32_t)((nb0 + 8 * ng) * 144 + ks * 32) + boff;
            uint32_t b[2];
            // r gate
            ldsm2(b, Wu + 0 * TILE_B + no);   // ih_r_hi : axh, axl
            mma16816(ar[0][ng], axh[0], b);  mma16816(ar[1][ng], axh[1], b);
            mma16816(ar[0][ng], axl[0], b);  mma16816(ar[1][ng], axl[1], b);
            ldsm2(b, Wu + 3 * TILE_B + no);   // ih_r_lo : axh
            mma16816(ar[0][ng], axh[0], b);  mma16816(ar[1][ng], axh[1], b);
            ldsm2(b, Wu + 6 * TILE_B + no);   // hh_r_hi : ahh, ahl
            mma16816(ar[0][ng], ahh[0], b);  mma16816(ar[1][ng], ahh[1], b);
            mma16816(ar[0][ng], ahl[0], b);  mma16816(ar[1][ng], ahl[1], b);
            ldsm2(b, Wu + 9 * TILE_B + no);   // hh_r_lo : ahh
            mma16816(ar[0][ng], ahh[0], b);  mma16816(ar[1][ng], ahh[1], b);
            // z gate
            ldsm2(b, Wu + 1 * TILE_B + no);
            mma16816(az[0][ng], axh[0], b);  mma16816(az[1][ng], axh[1], b);
            mma16816(az[0][ng], axl[0], b);  mma16816(az[1][ng], axl[1], b);
            ldsm2(b, Wu + 4 * TILE_B + no);
            mma16816(az[0][ng], axh[0], b);  mma16816(az[1][ng], axh[1], b);
            ldsm2(b, Wu + 7 * TILE_B + no);
            mma16816(az[0][ng], ahh[0], b);  mma16816(az[1][ng], ahh[1], b);
            mma16816(az[0][ng], ahl[0], b);  mma16816(az[1][ng], ahl[1], b);
            ldsm2(b, Wu + 10 * TILE_B + no);
            mma16816(az[0][ng], ahh[0], b);  mma16816(az[1][ng], ahh[1], b);
            // n gate (input part)
            ldsm2(b, Wu + 2 * TILE_B + no);
            mma16816(ani[0][ng], axh[0], b);  mma16816(ani[1][ng], axh[1], b);
            mma16816(ani[0][ng], axl[0], b);  mma16816(ani[1][ng], axl[1], b);
            ldsm2(b, Wu + 5 * TILE_B + no);
            mma16816(ani[0][ng], axh[0], b);  mma16816(ani[1][ng], axh[1], b);
            // n gate (hidden part)
            ldsm2(b, Wu + 8 * TILE_B + no);
            mma16816(anh[0][ng], ahh[0], b);  mma16816(anh[1][ng], ahh[1], b);
            mma16816(anh[0][ng], ahl[0], b);  mma16816(anh[1][ng], ahl[1], b);
            ldsm2(b, Wu + 11 * TILE_B + no);
            mma16816(anh[0][ng], ahh[0], b);  mma16816(anh[1][ng], ahh[1], b);
        }
    }

    // ---- fused epilogue: gates, mask, new_h, value partials ----
    const __nv_bfloat16* HHIh = (const __nv_bfloat16*)HHI;
    const __nv_bfloat16* HLOh = (const __nv_bfloat16*)HLO;
    float vp[4] = {0.0f, 0.0f, 0.0f, 0.0f};
    int mk[4];
#pragma unroll
    for (int st = 0; st < 2; ++st) {
        mk[st * 2]     = mask[row0 + rbase + 16 * st + g];
        mk[st * 2 + 1] = mask[row0 + rbase + 16 * st + g + 8];
    }
#pragma unroll
    for (int st = 0; st < 2; ++st)
#pragma unroll
        for (int ng = 0; ng < 2; ++ng)
#pragma unroll
            for (int e = 0; e < 4; ++e) {
                int half = e >> 1;
                int row  = rbase + 16 * st + g + 8 * half;
                int c    = nb0 + 8 * ng + 2 * tq + (e & 1);
                float rr = fsigm(ar[st][ng][e] + BIH[c] + BHH[c]);
                float zz = fsigm(az[st][ng][e] + BIH[64 + c] + BHH[64 + c]);
                float nn = ftanh(ani[st][ng][e] + BIH[128 + c] + rr * (anh[st][ng][e] + BHH[128 + c]));
                float hold = __bfloat162float(HHIh[row * 72 + c]) + __bfloat162float(HLOh[row * 72 + c]);
                float hg = (1.0f - zz) * nn + zz * hold;
                float hn = mk[st * 2 + half] ? hg : hold;
                HSN[row * 65 + c] = hn;
                vp[st * 2 + half] += hn * W2[c];
            }

    // quad reduce and stage value partials
#pragma unroll
    for (int off = 1; off <= 2; off <<= 1)
#pragma unroll
        for (int q = 0; q < 4; ++q) vp[q] += __shfl_xor_sync(0xffffffffu, vp[q], off);
    if (tq == 0) {
#pragma unroll
        for (int st = 0; st < 2; ++st) {
            VP[(rbase + 16 * st + g) * 4 + nq]     = vp[st * 2];
            VP[(rbase + 16 * st + g + 8) * 4 + nq] = vp[st * 2 + 1];
        }
    }
    __syncthreads();

    // ---- final stores ----
    if (tid < 128)
        vout[row0 + tid] = VP[tid * 4] + VP[tid * 4 + 1] + VP[tid * 4 + 2] + VP[tid * 4 + 3] + bf2[0];
#pragma unroll
    for (int it = 0; it < 16; ++it) {
        int i = tid + it * NT;           // 8192
        int r = i >> 6, c = i & 63;
        hout[(size_t)(row0 + r) * 64 + c] = HSN[r * 65 + c];
    }
}

// ---------------- launch ----------------
extern "C" void kernel_launch(void* const* d_in, const int* in_sizes, int n_in,
                              void* d_out, int out_size) {
    const float* obs = (const float*)d_in[0];
    const float* h1  = (const float*)d_in[1];
    const float* h2  = (const float*)d_in[2];
    const int*   msk = (const int*)d_in[3];

    const int B = in_sizes[1] / 64;   // 262144

    float* out = (float*)d_out;
    float* v1  = out;
    float* v2  = out + (size_t)B;
    float* ho1 = out + 2 * (size_t)B;
    float* ho2 = ho1 + (size_t)B * 64;

    convert_weights_kernel<<<160, 256>>>(
        (const float*)d_in[4],  (const float*)d_in[6],  (const float*)d_in[7],
        (const float*)d_in[12], (const float*)d_in[14], (const float*)d_in[15]);

    cudaFuncSetAttribute(gru_hmma_kernel,
                         cudaFuncAttributeMaxDynamicSharedMemorySize, SMEM_TOTAL);

    dim3 grid((B / 128) * 2);
    gru_hmma_kernel<<<grid, NT, SMEM_TOTAL>>>(
        obs, h1, h2, msk,
        (const float*)d_in[8],  (const float*)d_in[9],
        (const float*)d_in[5],  (const float*)d_in[10], (const float*)d_in[11],
        (const float*)d_in[16], (const float*)d_in[17],
        (const float*)d_in[13], (const float*)d_in[18], (const float*)d_in[19],
        v1, v2, ho1, ho2);
}

// round 7
// speedup vs baseline: 5.0720x; 1.2462x over previous
#include <cuda_runtime.h>
#include <cuda_bf16.h>
#include <stdint.h>

#define NT 512
#define NCTA 148
#define HCTA 74

// ---------------- math helpers ----------------
__device__ __forceinline__ float fsigm(float x) { return __fdividef(1.0f, 1.0f + __expf(-x)); }
__device__ __forceinline__ float ftanh(float x) {
    return 1.0f - __fdividef(2.0f, __expf(2.0f * x) + 1.0f);
}
__device__ __forceinline__ void split2(float a, float b, uint32_t& hi, uint32_t& lo) {
    __nv_bfloat16 ah = __float2bfloat16(a);
    __nv_bfloat16 bh = __float2bfloat16(b);
    __nv_bfloat16 al = __float2bfloat16(a - __bfloat162float(ah));
    __nv_bfloat16 bl = __float2bfloat16(b - __bfloat162float(bh));
    hi = ((uint32_t)__bfloat16_as_ushort(bh) << 16) | __bfloat16_as_ushort(ah);
    lo = ((uint32_t)__bfloat16_as_ushort(bl) << 16) | __bfloat16_as_ushort(al);
}
__device__ __forceinline__ uint32_t smem_u32(const void* p) {
    uint32_t a;
    asm("{ .reg .u64 t; cvta.to.shared.u64 t, %1; cvt.u32.u64 %0, t; }" : "=r"(a) : "l"(p));
    return a;
}

// ---------------- mma + ldmatrix ----------------
__device__ __forceinline__ void mma16816(float* c, const uint32_t* a, const uint32_t* b) {
    asm volatile(
        "mma.sync.aligned.m16n8k16.row.col.f32.bf16.bf16.f32 "
        "{%0,%1,%2,%3}, {%4,%5,%6,%7}, {%8,%9}, {%0,%1,%2,%3};"
        : "+f"(c[0]), "+f"(c[1]), "+f"(c[2]), "+f"(c[3])
        : "r"(a[0]), "r"(a[1]), "r"(a[2]), "r"(a[3]), "r"(b[0]), "r"(b[1]));
}
__device__ __forceinline__ void ldsm4(uint32_t* d, uint32_t addr) {
    asm volatile("ldmatrix.sync.aligned.m8n8.x4.shared.b16 {%0,%1,%2,%3}, [%4];"
                 : "=r"(d[0]), "=r"(d[1]), "=r"(d[2]), "=r"(d[3]) : "r"(addr));
}
__device__ __forceinline__ void ldsm2(uint32_t* d, uint32_t addr) {
    asm volatile("ldmatrix.sync.aligned.m8n8.x2.shared.b16 {%0,%1}, [%2];"
                 : "=r"(d[0]), "=r"(d[1]) : "r"(addr));
}

// ---------------- weight scratch: swizzled [64][64] bf16 tiles, 8KB each ------
// half-index for (row n, col k): n*64 + ((k>>3 ^ (n&7))<<3) + (k&7)
#define TILE_B 8192
#define TILE_H 4096
__device__ __align__(16) __nv_bfloat16 g_wt[2][20][TILE_H];

__global__ void convert_weights_kernel(
    const float* __restrict__ fc1a, const float* __restrict__ wiha, const float* __restrict__ whha,
    const float* __restrict__ fc1b, const float* __restrict__ wihb, const float* __restrict__ whhb)
{
    int tid = blockIdx.x * blockDim.x + threadIdx.x;
    int stride = gridDim.x * blockDim.x;
    for (int s = 0; s < 2; ++s) {
        const float* fc1 = s ? fc1b : fc1a;
        const float* wih = s ? wihb : wiha;
        const float* whh = s ? whhb : whha;
        for (int e = tid; e < 40960; e += stride) {
            float v; int th, tl, n, k;
            if (e < 16384) {                        // fc1 [64,256] -> tiles 0..7
                n = e >> 8; int kf = e & 255; int kc = kf >> 6; k = kf & 63;
                v = fc1[e]; th = kc; tl = 4 + kc;
            } else if (e < 28672) {                 // wih [192,64] -> tiles 8..13
                int e2 = e - 16384, j = e2 >> 6; k = e2 & 63; int gg = j >> 6; n = j & 63;
                v = wih[e2]; th = 8 + gg; tl = 11 + gg;
            } else {                                // whh [192,64] -> tiles 14..19
                int e2 = e - 28672, j = e2 >> 6; k = e2 & 63; int gg = j >> 6; n = j & 63;
                v = whh[e2]; th = 14 + gg; tl = 17 + gg;
            }
            uint32_t off = n * 64 + (((k >> 3) ^ (n & 7)) << 3) + (k & 7);
            __nv_bfloat16 hi = __float2bfloat16(v);
            __nv_bfloat16 lo = __float2bfloat16(v - __bfloat162float(hi));
            g_wt[s][th][off] = hi;
            g_wt[s][tl][off] = lo;
        }
    }
}

// ---------------- smem layout (bytes) ----------------
// weight slots: 0-3 fc1_hi(kc) 4-7 fc1_lo(kc)
//   8=ih_r_hi 9=ih_z_hi 10=ih_n_hi 11=ih_r_lo 12=ih_z_lo 13=ih_n_lo
//  14=hh_r_hi 15=hh_z_hi 16=hh_n_hi 17=hh_r_lo 18=hh_z_lo 19=hh_n_lo
#define SM_W    0                 // 20 tiles = 163840
#define SM_XHI  163840            // plane [128 rows][128 B] = 16384
#define SM_XLO  180224
#define SM_HHI  196608
#define SM_HLO  212992
#define SM_BIH  229376            // float[192]
#define SM_BHH  230144            // float[192]
#define SM_B1   230912            // float[64]
#define SM_W2   231168            // float[64]
#define SMEM_TOTAL 231424
// overlays (barrier-separated): HSN fp32[128][64] on XHI+XLO; VP float[128][4] on HHI

__global__ __launch_bounds__(NT, 1)
void gru_hmma_kernel(
    const float* __restrict__ obs, const float* __restrict__ h1, const float* __restrict__ h2,
    const int* __restrict__ mask,
    const float* __restrict__ bih1, const float* __restrict__ bhh1,
    const float* __restrict__ bfc1_1, const float* __restrict__ wfc2_1, const float* __restrict__ bfc2_1,
    const float* __restrict__ bih2, const float* __restrict__ bhh2,
    const float* __restrict__ bfc1_2, const float* __restrict__ wfc2_2, const float* __restrict__ bfc2_2,
    float* __restrict__ v1, float* __restrict__ v2,
    float* __restrict__ ho1, float* __restrict__ ho2,
    int ntiles)
{
    extern __shared__ __align__(16) unsigned char sm[];
    unsigned char* XHI = sm + SM_XHI;
    unsigned char* XLO = sm + SM_XLO;
    unsigned char* HHI = sm + SM_HHI;
    unsigned char* HLO = sm + SM_HLO;
    float* HSN = (float*)(sm + SM_XHI);     // overlay
    float* VP  = (float*)(sm + SM_HHI);     // overlay
    float* BIH = (float*)(sm + SM_BIH);
    float* BHH = (float*)(sm + SM_BHH);
    float* B1  = (float*)(sm + SM_B1);
    float* W2  = (float*)(sm + SM_W2);

    const int tid  = threadIdx.x;
    const int wid  = tid >> 5;
    const int lane = tid & 31;
    const int g    = lane >> 2;
    const int tq   = lane & 3;

    const int ms  = wid & 3;            // row quarter: rows 32ms..32ms+31
    const int nq  = wid >> 2;           // col quarter: cols 16nq..16nq+15
    const int rbase = 32 * ms;
    const int nb0   = 16 * nq;

    // ldmatrix per-lane row/chunk components
    const int rowa = (lane & 7) + 8 * ((lane >> 3) & 1);   // A frag row within 16-strip
    const int cca  = lane >> 4;                             // A k-chunk sub
    const int rowb = lane & 7;                              // B frag row within 8
    const int ccb  = (lane >> 3) & 1;
    const int swa  = lane & 7;                              // XOR key = row&7
    const int swb  = lane & 7;

    const uint32_t smb  = smem_u32(sm);
    const uint32_t Wu   = smb + SM_W;
    const uint32_t XHIu = smb + SM_XHI;
    const uint32_t XLOu = smb + SM_XLO;
    const uint32_t HHIu = smb + SM_HHI;
    const uint32_t HLOu = smb + SM_HLO;

    const int stream = (blockIdx.x >= HCTA) ? 1 : 0;
    const int local  = blockIdx.x - HCTA * stream;

    const float* hin = stream ? h2 : h1;
    const float* bih = stream ? bih2 : bih1;
    const float* bhh = stream ? bhh2 : bhh1;
    const float* bf1 = stream ? bfc1_2 : bfc1_1;
    const float* wf2 = stream ? wfc2_2 : wfc2_1;
    const float* bf2 = stream ? bfc2_2 : bfc2_1;
    float* vout = stream ? v2 : v1;
    float* hout = stream ? ho2 : ho1;

    // ---- one-time: all 20 weight tiles + biases into smem ----
    {
        const int4* src = (const int4*)&g_wt[stream][0][0];
        int4* dst = (int4*)sm;
        for (int i = tid; i < (20 * TILE_B) / 16; i += NT) dst[i] = src[i];
    }
    for (int i = tid; i < 192; i += NT) { BIH[i] = bih[i]; BHH[i] = bhh[i]; }
    if (tid < 64) { B1[tid] = bf1[tid]; W2[tid] = wf2[tid]; }
    const float bias2 = bf2[0];
    __syncthreads();

    for (int tile = local; tile < ntiles; tile += HCTA) {
        const int row0 = tile * 128;

        // ---- Phase A: H tile -> HHI/HLO planes ----
#pragma unroll
        for (int it = 0; it < 4; ++it) {
            int idx4 = tid + it * NT;                // 2048 float4s = 128x64
            int r = idx4 >> 4, c4 = idx4 & 15;
            float4 v = *(const float4*)(hin + (size_t)(row0 + r) * 64 + 4 * c4);
            uint32_t hi01, lo01, hi23, lo23;
            split2(v.x, v.y, hi01, lo01);
            split2(v.z, v.w, hi23, lo23);
            uint32_t off = (uint32_t)(r * 128 + (((c4 >> 1) ^ (r & 7)) << 4) + (c4 & 1) * 8);
            *(uint32_t*)(HHI + off)     = hi01;  *(uint32_t*)(HHI + off + 4) = hi23;
            *(uint32_t*)(HLO + off)     = lo01;  *(uint32_t*)(HLO + off + 4) = lo23;
        }

        // ---- Phase B: fc1 GEMM (K=256, 4 chunks) with obs register prefetch ----
        float acc1[2][2][4];
#pragma unroll
        for (int st = 0; st < 2; ++st)
#pragma unroll
            for (int ng = 0; ng < 2; ++ng)
#pragma unroll
                for (int e = 0; e < 4; ++e) acc1[st][ng][e] = 0.0f;

        float4 pre[4];
#pragma unroll
        for (int it = 0; it < 4; ++it) {
            int idx4 = tid + it * NT;
            int r = idx4 >> 4, c4 = idx4 & 15;
            pre[it] = *(const float4*)(obs + (size_t)(row0 + r) * 256 + 4 * c4);
        }

        for (int kc = 0; kc < 4; ++kc) {
            __syncthreads();   // prev chunk fully consumed (or Phase A writes done)
#pragma unroll
            for (int it = 0; it < 4; ++it) {
                int idx4 = tid + it * NT;
                int r = idx4 >> 4, c4 = idx4 & 15;
                uint32_t hi01, lo01, hi23, lo23;
                split2(pre[it].x, pre[it].y, hi01, lo01);
                split2(pre[it].z, pre[it].w, hi23, lo23);
                uint32_t off = (uint32_t)(r * 128 + (((c4 >> 1) ^ (r & 7)) << 4) + (c4 & 1) * 8);
                *(uint32_t*)(XHI + off)     = hi01;  *(uint32_t*)(XHI + off + 4) = hi23;
                *(uint32_t*)(XLO + off)     = lo01;  *(uint32_t*)(XLO + off + 4) = lo23;
            }
            __syncthreads();
            if (kc < 3) {
#pragma unroll
                for (int it = 0; it < 4; ++it) {
                    int idx4 = tid + it * NT;
                    int r = idx4 >> 4, c4 = idx4 & 15;
                    pre[it] = *(const float4*)(obs + (size_t)(row0 + r) * 256 + (kc + 1) * 64 + 4 * c4);
                }
            }
            const uint32_t bth = Wu + (uint32_t)kc * TILE_B;
            const uint32_t btl = Wu + (uint32_t)(4 + kc) * TILE_B;
#pragma unroll 1
            for (int ks = 0; ks < 4; ++ks) {
                uint32_t xh[2][4], xl[2][4];
#pragma unroll
                for (int st = 0; st < 2; ++st) {
                    uint32_t ro = (uint32_t)((rbase + 16 * st + rowa) * 128 +
                                             (((ks * 2 + cca) ^ swa) << 4));
                    ldsm4(xh[st], XHIu + ro);
                    ldsm4(xl[st], XLOu + ro);
                }
#pragma unroll
                for (int ng = 0; ng < 2; ++ng) {
                    uint32_t no = (uint32_t)((nb0 + 8 * ng + rowb) * 128 +
                                             (((ks * 2 + ccb) ^ swb) << 4));
                    uint32_t bh[2], bl[2];
                    ldsm2(bh, bth + no);
                    ldsm2(bl, btl + no);
                    mma16816(acc1[0][ng], xh[0], bh);  mma16816(acc1[1][ng], xh[1], bh);
                    mma16816(acc1[0][ng], xh[0], bl);  mma16816(acc1[1][ng], xh[1], bl);
                    mma16816(acc1[0][ng], xl[0], bh);  mma16816(acc1[1][ng], xl[1], bh);
                }
            }
        }
        __syncthreads();   // fc1 mma reads done; X planes reusable

        // ---- Phase C: X = tanh(acc+b) -> X planes ----
#pragma unroll
        for (int st = 0; st < 2; ++st)
#pragma unroll
            for (int ng = 0; ng < 2; ++ng) {
                int col = nb0 + 8 * ng + 2 * tq;
                int ra = rbase + 16 * st + g;
                int rb = ra + 8;
                float x0 = ftanh(acc1[st][ng][0] + B1[col]);
                float x1 = ftanh(acc1[st][ng][1] + B1[col + 1]);
                float x2 = ftanh(acc1[st][ng][2] + B1[col]);
                float x3 = ftanh(acc1[st][ng][3] + B1[col + 1]);
                uint32_t hi01, lo01, hi23, lo23;
                split2(x0, x1, hi01, lo01);
                split2(x2, x3, hi23, lo23);
                uint32_t offa = (uint32_t)(ra * 128 + ((((col >> 3)) ^ (ra & 7)) << 4) + (col & 7) * 2);
                uint32_t offb = (uint32_t)(rb * 128 + ((((col >> 3)) ^ (rb & 7)) << 4) + (col & 7) * 2);
                *(uint32_t*)(XHI + offa) = hi01;  *(uint32_t*)(XLO + offa) = lo01;
                *(uint32_t*)(XHI + offb) = hi23;  *(uint32_t*)(XLO + offb) = lo23;
            }
        __syncthreads();

        // ---- Phase E: GRU gate GEMMs ----
        float ar[2][2][4], az[2][2][4], ani[2][2][4], anh[2][2][4];
#pragma unroll
        for (int st = 0; st < 2; ++st)
#pragma unroll
            for (int ng = 0; ng < 2; ++ng)
#pragma unroll
                for (int e = 0; e < 4; ++e) {
                    ar[st][ng][e] = az[st][ng][e] = ani[st][ng][e] = anh[st][ng][e] = 0.0f;
                }

#pragma unroll 1
        for (int ks = 0; ks < 4; ++ks) {
            uint32_t axh[2][4], axl[2][4], ahh[2][4], ahl[2][4];
#pragma unroll
            for (int st = 0; st < 2; ++st) {
                uint32_t ro = (uint32_t)((rbase + 16 * st + rowa) * 128 +
                                         (((ks * 2 + cca) ^ swa) << 4));
                ldsm4(axh[st], XHIu + ro);
                ldsm4(axl[st], XLOu + ro);
                ldsm4(ahh[st], HHIu + ro);
                ldsm4(ahl[st], HLOu + ro);
            }
#pragma unroll
            for (int ng = 0; ng < 2; ++ng) {
                uint32_t no = (uint32_t)((nb0 + 8 * ng + rowb) * 128 +
                                         (((ks * 2 + ccb) ^ swb) << 4));
                uint32_t b[2];
                // r gate
                ldsm2(b, Wu + 8 * TILE_B + no);    // ih_r_hi
                mma16816(ar[0][ng], axh[0], b);  mma16816(ar[1][ng], axh[1], b);
                mma16816(ar[0][ng], axl[0], b);  mma16816(ar[1][ng], axl[1], b);
                ldsm2(b, Wu + 11 * TILE_B + no);   // ih_r_lo
                mma16816(ar[0][ng], axh[0], b);  mma16816(ar[1][ng], axh[1], b);
                ldsm2(b, Wu + 14 * TILE_B + no);   // hh_r_hi
                mma16816(ar[0][ng], ahh[0], b);  mma16816(ar[1][ng], ahh[1], b);
                mma16816(ar[0][ng], ahl[0], b);  mma16816(ar[1][ng], ahl[1], b);
                ldsm2(b, Wu + 17 * TILE_B + no);   // hh_r_lo
                mma16816(ar[0][ng], ahh[0], b);  mma16816(ar[1][ng], ahh[1], b);
                // z gate
                ldsm2(b, Wu + 9 * TILE_B + no);
                mma16816(az[0][ng], axh[0], b);  mma16816(az[1][ng], axh[1], b);
                mma16816(az[0][ng], axl[0], b);  mma16816(az[1][ng], axl[1], b);
                ldsm2(b, Wu + 12 * TILE_B + no);
                mma16816(az[0][ng], axh[0], b);  mma16816(az[1][ng], axh[1], b);
                ldsm2(b, Wu + 15 * TILE_B + no);
                mma16816(az[0][ng], ahh[0], b);  mma16816(az[1][ng], ahh[1], b);
                mma16816(az[0][ng], ahl[0], b);  mma16816(az[1][ng], ahl[1], b);
                ldsm2(b, Wu + 18 * TILE_B + no);
                mma16816(az[0][ng], ahh[0], b);  mma16816(az[1][ng], ahh[1], b);
                // n gate (input)
                ldsm2(b, Wu + 10 * TILE_B + no);
                mma16816(ani[0][ng], axh[0], b);  mma16816(ani[1][ng], axh[1], b);
                mma16816(ani[0][ng], axl[0], b);  mma16816(ani[1][ng], axl[1], b);
                ldsm2(b, Wu + 13 * TILE_B + no);
                mma16816(ani[0][ng], axh[0], b);  mma16816(ani[1][ng], axh[1], b);
                // n gate (hidden)
                ldsm2(b, Wu + 16 * TILE_B + no);
                mma16816(anh[0][ng], ahh[0], b);  mma16816(anh[1][ng], ahh[1], b);
                mma16816(anh[0][ng], ahl[0], b);  mma16816(anh[1][ng], ahl[1], b);
                ldsm2(b, Wu + 19 * TILE_B + no);
                mma16816(anh[0][ng], ahh[0], b);  mma16816(anh[1][ng], ahh[1], b);
            }
        }
        __syncthreads();   // all MMA reads of X planes done (HSN overlay safe)

        // ---- epilogue: gates, mask, new_h -> HSN, value partials ----
        const __nv_bfloat16* HHIh = (const __nv_bfloat16*)HHI;
        const __nv_bfloat16* HLOh = (const __nv_bfloat16*)HLO;
        float vp[4] = {0.0f, 0.0f, 0.0f, 0.0f};
        int mk[4];
#pragma unroll
        for (int st = 0; st < 2; ++st) {
            mk[st * 2]     = mask[row0 + rbase + 16 * st + g];
            mk[st * 2 + 1] = mask[row0 + rbase + 16 * st + g + 8];
        }
#pragma unroll
        for (int st = 0; st < 2; ++st)
#pragma unroll
            for (int ng = 0; ng < 2; ++ng)
#pragma unroll
                for (int e = 0; e < 4; ++e) {
                    int half = e >> 1;
                    int row  = rbase + 16 * st + g + 8 * half;
                    int c    = nb0 + 8 * ng + 2 * tq + (e & 1);
                    float rr = fsigm(ar[st][ng][e] + BIH[c] + BHH[c]);
                    float zz = fsigm(az[st][ng][e] + BIH[64 + c] + BHH[64 + c]);
                    float nn = ftanh(ani[st][ng][e] + BIH[128 + c] +
                                     rr * (anh[st][ng][e] + BHH[128 + c]));
                    uint32_t hidx = (uint32_t)(row * 64 + (((c >> 3) ^ (row & 7)) << 3) + (c & 7));
                    float hold = __bfloat162float(HHIh[hidx]) + __bfloat162float(HLOh[hidx]);
                    float hg = (1.0f - zz) * nn + zz * hold;
                    float hn = mk[st * 2 + half] ? hg : hold;
                    HSN[row * 64 + c] = hn;
                    vp[st * 2 + half] += hn * W2[c];
                }

        // quad reduce
#pragma unroll
        for (int off = 1; off <= 2; off <<= 1)
#pragma unroll
            for (int q = 0; q < 4; ++q) vp[q] += __shfl_xor_sync(0xffffffffu, vp[q], off);

        __syncthreads();   // all HHI hold-reads done (VP overlay safe)
        if (tq == 0) {
#pragma unroll
            for (int st = 0; st < 2; ++st) {
                VP[(rbase + 16 * st + g) * 4 + nq]     = vp[st * 2];
                VP[(rbase + 16 * st + g + 8) * 4 + nq] = vp[st * 2 + 1];
            }
        }
        __syncthreads();

        // ---- final stores ----
        if (tid < 128)
            vout[row0 + tid] = VP[tid * 4] + VP[tid * 4 + 1] + VP[tid * 4 + 2] + VP[tid * 4 + 3] + bias2;
#pragma unroll
        for (int it = 0; it < 16; ++it) {
            int i = tid + it * NT;           // 8192
            int r = i >> 6, c = i & 63;
            hout[(size_t)(row0 + r) * 64 + c] = HSN[r * 64 + c];
        }
        __syncthreads();   // HSN/VP reads done before next tile overwrites planes
    }
}

// ---------------- launch ----------------
extern "C" void kernel_launch(void* const* d_in, const int* in_sizes, int n_in,
                              void* d_out, int out_size) {
    const float* obs = (const float*)d_in[0];
    const float* h1  = (const float*)d_in[1];
    const float* h2  = (const float*)d_in[2];
    const int*   msk = (const int*)d_in[3];

    const int B = in_sizes[1] / 64;   // 262144
    const int ntiles = B / 128;       // 2048

    float* out = (float*)d_out;
    float* v1  = out;
    float* v2  = out + (size_t)B;
    float* ho1 = out + 2 * (size_t)B;
    float* ho2 = ho1 + (size_t)B * 64;

    convert_weights_kernel<<<160, 256>>>(
        (const float*)d_in[4],  (const float*)d_in[6],  (const float*)d_in[7],
        (const float*)d_in[12], (const float*)d_in[14], (const float*)d_in[15]);

    cudaFuncSetAttribute(gru_hmma_kernel,
                         cudaFuncAttributeMaxDynamicSharedMemorySize, SMEM_TOTAL);

    gru_hmma_kernel<<<NCTA, NT, SMEM_TOTAL>>>(
        obs, h1, h2, msk,
        (const float*)d_in[8],  (const float*)d_in[9],
        (const float*)d_in[5],  (const float*)d_in[10], (const float*)d_in[11],
        (const float*)d_in[16], (const float*)d_in[17],
        (const float*)d_in[13], (const float*)d_in[18], (const float*)d_in[19],
        v1, v2, ho1, ho2, ntiles);
}

// round 8
// speedup vs baseline: 6.0899x; 1.2007x over previous
#include <cuda_runtime.h>
#include <cuda_bf16.h>
#include <stdint.h>

#define NT 512
#define NCTA 148
#define HCTA 74

// ---------------- math helpers ----------------
__device__ __forceinline__ float fsigm(float x) { return __fdividef(1.0f, 1.0f + __expf(-x)); }
__device__ __forceinline__ float ftanh(float x) {
    return 1.0f - __fdividef(2.0f, __expf(2.0f * x) + 1.0f);
}
__device__ __forceinline__ uint32_t cvt_bf16x2(float x, float y) {   // lo=x, hi=y
    uint32_t r;
    asm("cvt.rn.bf16x2.f32 %0, %1, %2;" : "=r"(r) : "f"(y), "f"(x));
    return r;
}
__device__ __forceinline__ void split2f(float a, float b, uint32_t& hi, uint32_t& lo) {
    hi = cvt_bf16x2(a, b);
    float af = __uint_as_float(hi << 16);
    float bf = __uint_as_float(hi & 0xffff0000u);
    lo = cvt_bf16x2(a - af, b - bf);
}
__device__ __forceinline__ uint32_t smem_u32(const void* p) {
    uint32_t a;
    asm("{ .reg .u64 t; cvta.to.shared.u64 t, %1; cvt.u32.u64 %0, t; }" : "=r"(a) : "l"(p));
    return a;
}

// ---------------- mma + ldmatrix ----------------
__device__ __forceinline__ void mma16816(float* c, const uint32_t* a, const uint32_t* b) {
    asm volatile(
        "mma.sync.aligned.m16n8k16.row.col.f32.bf16.bf16.f32 "
        "{%0,%1,%2,%3}, {%4,%5,%6,%7}, {%8,%9}, {%0,%1,%2,%3};"
        : "+f"(c[0]), "+f"(c[1]), "+f"(c[2]), "+f"(c[3])
        : "r"(a[0]), "r"(a[1]), "r"(a[2]), "r"(a[3]), "r"(b[0]), "r"(b[1]));
}
__device__ __forceinline__ void ldsm4(uint32_t* d, uint32_t addr) {
    asm volatile("ldmatrix.sync.aligned.m8n8.x4.shared.b16 {%0,%1,%2,%3}, [%4];"
                 : "=r"(d[0]), "=r"(d[1]), "=r"(d[2]), "=r"(d[3]) : "r"(addr));
}
__device__ __forceinline__ void ldsm2(uint32_t* d, uint32_t addr) {
    asm volatile("ldmatrix.sync.aligned.m8n8.x2.shared.b16 {%0,%1}, [%2];"
                 : "=r"(d[0]), "=r"(d[1]) : "r"(addr));
}

// ---------------- weight scratch: swizzled [64][64] bf16 tiles, 8KB each ------
// half-index for (row n, col k): n*64 + ((k>>3 ^ (n&7))<<3) + (k&7)
#define TILE_B 8192
#define TILE_H 4096
__device__ __align__(16) __nv_bfloat16 g_wt[2][20][TILE_H];

__global__ void convert_weights_kernel(
    const float* __restrict__ fc1a, const float* __restrict__ wiha, const float* __restrict__ whha,
    const float* __restrict__ fc1b, const float* __restrict__ wihb, const float* __restrict__ whhb)
{
    int tid = blockIdx.x * blockDim.x + threadIdx.x;
    int stride = gridDim.x * blockDim.x;
    for (int s = 0; s < 2; ++s) {
        const float* fc1 = s ? fc1b : fc1a;
        const float* wih = s ? wihb : wiha;
        const float* whh = s ? whhb : whha;
        for (int e = tid; e < 40960; e += stride) {
            float v; int th, tl, n, k;
            if (e < 16384) {                        // fc1 [64,256] -> tiles 0..7
                n = e >> 8; int kf = e & 255; int kc = kf >> 6; k = kf & 63;
                v = fc1[e]; th = kc; tl = 4 + kc;
            } else if (e < 28672) {                 // wih [192,64] -> tiles 8..13
                int e2 = e - 16384, j = e2 >> 6; k = e2 & 63; int gg = j >> 6; n = j & 63;
                v = wih[e2]; th = 8 + gg; tl = 11 + gg;
            } else {                                // whh [192,64] -> tiles 14..19
                int e2 = e - 28672, j = e2 >> 6; k = e2 & 63; int gg = j >> 6; n = j & 63;
                v = whh[e2]; th = 14 + gg; tl = 17 + gg;
            }
            uint32_t off = n * 64 + (((k >> 3) ^ (n & 7)) << 3) + (k & 7);
            __nv_bfloat16 hi = __float2bfloat16(v);
            __nv_bfloat16 lo = __float2bfloat16(v - __bfloat162float(hi));
            g_wt[s][th][off] = hi;
            g_wt[s][tl][off] = lo;
        }
    }
}

// ---------------- smem layout (bytes) ----------------
#define SM_W    0                 // 20 tiles = 163840
#define SM_X    163840            // 32KB region:
                                  //  Phase B: buf0 hi/lo @ +0/+8K, buf1 hi/lo @ +16K/+24K
                                  //  Phase C/E: XHI @ +0 (16K), XLO @ +16K (16K)
                                  //  VP overlay @ +24K (2KB)
#define SM_HHI  196608            // [128 rows][128 B]
#define SM_HLO  212992
#define SM_BIH  229376            // float[192]
#define SM_BHH  230144            // float[192]
#define SM_B1   230912            // float[64]
#define SM_W2   231168            // float[64]
#define SMEM_TOTAL 231424

__global__ __launch_bounds__(NT, 1)
void gru_hmma_kernel(
    const float* __restrict__ obs, const float* __restrict__ h1, const float* __restrict__ h2,
    const int* __restrict__ mask,
    const float* __restrict__ bih1, const float* __restrict__ bhh1,
    const float* __restrict__ bfc1_1, const float* __restrict__ wfc2_1, const float* __restrict__ bfc2_1,
    const float* __restrict__ bih2, const float* __restrict__ bhh2,
    const float* __restrict__ bfc1_2, const float* __restrict__ wfc2_2, const float* __restrict__ bfc2_2,
    float* __restrict__ v1, float* __restrict__ v2,
    float* __restrict__ ho1, float* __restrict__ ho2,
    int ntiles)
{
    extern __shared__ __align__(16) unsigned char sm[];
    unsigned char* XHI = sm + SM_X;
    unsigned char* XLO = sm + SM_X + 16384;
    unsigned char* HHI = sm + SM_HHI;
    unsigned char* HLO = sm + SM_HLO;
    float* VP  = (float*)(sm + SM_X + 24576);
    float* BIH = (float*)(sm + SM_BIH);
    float* BHH = (float*)(sm + SM_BHH);
    float* B1  = (float*)(sm + SM_B1);
    float* W2  = (float*)(sm + SM_W2);

    const int tid  = threadIdx.x;
    const int wid  = tid >> 5;
    const int lane = tid & 31;
    const int g    = lane >> 2;
    const int tq   = lane & 3;

    const int ms  = wid & 3;            // row quarter: rows 32ms..32ms+31
    const int nq  = wid >> 2;           // col quarter: cols 16nq..16nq+15
    const int rbase = 32 * ms;
    const int nb0   = 16 * nq;

    // ldmatrix per-lane components
    const int rowa = (lane & 7) + 8 * ((lane >> 3) & 1);   // A frag row within 16-strip
    const int cca  = lane >> 4;                             // A granule sub (0,1)
    const int rowb = lane & 7;                              // B frag row within 8
    const int ccb  = (lane >> 3) & 1;

    const uint32_t smb  = smem_u32(sm);
    const uint32_t Wu   = smb + SM_W;
    const uint32_t Xu   = smb + SM_X;
    const uint32_t XHIu = Xu;
    const uint32_t XLOu = Xu + 16384;
    const uint32_t HHIu = smb + SM_HHI;
    const uint32_t HLOu = smb + SM_HLO;

    const int stream = (blockIdx.x >= HCTA) ? 1 : 0;
    const int local  = blockIdx.x - HCTA * stream;

    const float* hin = stream ? h2 : h1;
    const float* bih = stream ? bih2 : bih1;
    const float* bhh = stream ? bhh2 : bhh1;
    const float* bf1 = stream ? bfc1_2 : bfc1_1;
    const float* wf2 = stream ? wfc2_2 : wfc2_1;
    const float* bf2 = stream ? bfc2_2 : bfc2_1;
    float* vout = stream ? v2 : v1;
    float* hout = stream ? ho2 : ho1;

    // obs-conversion task: thread owns (row r, granule gg) of each 32-col chunk
    const int orow = tid >> 2;
    const int ogr  = tid & 3;
    const uint32_t obs_soff = (uint32_t)(orow * 64 + ((ogr ^ ((orow >> 1) & 3)) << 4));

    // ---- one-time: all 20 weight tiles + biases into smem ----
    {
        const int4* src = (const int4*)&g_wt[stream][0][0];
        int4* dst = (int4*)sm;
        for (int i = tid; i < (20 * TILE_B) / 16; i += NT) dst[i] = src[i];
    }
    for (int i = tid; i < 192; i += NT) { BIH[i] = bih[i]; BHH[i] = bhh[i]; }
    if (tid < 64) { B1[tid] = bf1[tid]; W2[tid] = wf2[tid]; }
    const float bias2 = bf2[0];
    __syncthreads();

    // ---- prologue for first tile: H planes + obs chunk0 prefetch ----
    float4 pre0, pre1;
    {
        const int row0 = local * 128;
#pragma unroll
        for (int it = 0; it < 2; ++it) {
            int idx = tid + it * NT;
            int r = idx >> 3, gg = idx & 7;
            const float* p = hin + (size_t)(row0 + r) * 64 + gg * 8;
            float4 v0 = *(const float4*)p;
            float4 v1 = *(const float4*)(p + 4);
            uint4 hi, lo;
            split2f(v0.x, v0.y, hi.x, lo.x);
            split2f(v0.z, v0.w, hi.y, lo.y);
            split2f(v1.x, v1.y, hi.z, lo.z);
            split2f(v1.z, v1.w, hi.w, lo.w);
            uint32_t off = (uint32_t)(r * 128 + ((gg ^ (r & 7)) << 4));
            *(uint4*)(HHI + off) = hi;
            *(uint4*)(HLO + off) = lo;
        }
        const float* p = obs + (size_t)(row0 + orow) * 256 + ogr * 8;
        pre0 = *(const float4*)p;
        pre1 = *(const float4*)(p + 4);
    }

    for (int tile = local; tile < ntiles; tile += HCTA) {
        const int row0 = tile * 128;

        // ---- Phase B: fc1 GEMM, K=256 in 8 chunks of 32, double-buffered ----
        float acc1[2][2][4];
#pragma unroll
        for (int st = 0; st < 2; ++st)
#pragma unroll
            for (int ng = 0; ng < 2; ++ng)
#pragma unroll
                for (int e = 0; e < 4; ++e) acc1[st][ng][e] = 0.0f;

        for (int kc = 0; kc < 8; ++kc) {
            // store prefetched chunk into ping-pong buffer
            {
                uint4 hi, lo;
                split2f(pre0.x, pre0.y, hi.x, lo.x);
                split2f(pre0.z, pre0.w, hi.y, lo.y);
                split2f(pre1.x, pre1.y, hi.z, lo.z);
                split2f(pre1.z, pre1.w, hi.w, lo.w);
                unsigned char* bb = sm + SM_X + (kc & 1) * 16384;
                *(uint4*)(bb + obs_soff) = hi;
                *(uint4*)(bb + 8192 + obs_soff) = lo;
            }
            if (kc < 7) {
                const float* p = obs + (size_t)(row0 + orow) * 256 + (kc + 1) * 32 + ogr * 8;
                pre0 = *(const float4*)p;
                pre1 = *(const float4*)(p + 4);
            }
            __syncthreads();

            const uint32_t bufh = Xu + (uint32_t)((kc & 1) * 16384);
            const uint32_t bufl = bufh + 8192;
            const uint32_t bth = Wu + (uint32_t)((kc >> 1)) * TILE_B;
            const uint32_t btl = Wu + (uint32_t)(4 + (kc >> 1)) * TILE_B;
#pragma unroll
            for (int ks = 0; ks < 2; ++ks) {
                uint32_t xh[2][4], xl[2][4];
#pragma unroll
                for (int st = 0; st < 2; ++st) {
                    int row = rbase + 16 * st + rowa;
                    uint32_t ro = (uint32_t)(row * 64 +
                                  (((ks * 2 + cca) ^ ((row >> 1) & 3)) << 4));
                    ldsm4(xh[st], bufh + ro);
                    ldsm4(xl[st], bufl + ro);
                }
#pragma unroll
                for (int ng = 0; ng < 2; ++ng) {
                    int n = nb0 + 8 * ng + rowb;
                    int gin = (kc & 1) * 4 + ks * 2 + ccb;
                    uint32_t no = (uint32_t)(n * 128 + ((gin ^ (n & 7)) << 4));
                    uint32_t bh[2], bl[2];
                    ldsm2(bh, bth + no);
                    ldsm2(bl, btl + no);
                    mma16816(acc1[0][ng], xh[0], bh);  mma16816(acc1[1][ng], xh[1], bh);
                    mma16816(acc1[0][ng], xh[0], bl);  mma16816(acc1[1][ng], xh[1], bl);
                    mma16816(acc1[0][ng], xl[0], bh);  mma16816(acc1[1][ng], xl[1], bh);
                }
            }
        }
        __syncthreads();   // last chunk MMA done; X region reusable for X planes

        // ---- Phase C: X = tanh(acc+b) -> X planes ([128][128B], ^(r&7) swizzle) ----
#pragma unroll
        for (int st = 0; st < 2; ++st)
#pragma unroll
            for (int ng = 0; ng < 2; ++ng) {
                int col = nb0 + 8 * ng + 2 * tq;
                int ra = rbase + 16 * st + g;
                int rb = ra + 8;
                float x0 = ftanh(acc1[st][ng][0] + B1[col]);
                float x1 = ftanh(acc1[st][ng][1] + B1[col + 1]);
                float x2 = ftanh(acc1[st][ng][2] + B1[col]);
                float x3 = ftanh(acc1[st][ng][3] + B1[col + 1]);
                uint32_t hi01, lo01, hi23, lo23;
                split2f(x0, x1, hi01, lo01);
                split2f(x2, x3, hi23, lo23);
                uint32_t offa = (uint32_t)(ra * 128 + (((col >> 3) ^ (ra & 7)) << 4) + (col & 7) * 2);
                uint32_t offb = (uint32_t)(rb * 128 + (((col >> 3) ^ (rb & 7)) << 4) + (col & 7) * 2);
                *(uint32_t*)(XHI + offa) = hi01;  *(uint32_t*)(XLO + offa) = lo01;
                *(uint32_t*)(XHI + offb) = hi23;  *(uint32_t*)(XLO + offb) = lo23;
            }
        __syncthreads();

        // ---- Phase E: GRU gate GEMMs ----
        float ar[2][2][4], az[2][2][4], ani[2][2][4], anh[2][2][4];
#pragma unroll
        for (int st = 0; st < 2; ++st)
#pragma unroll
            for (int ng = 0; ng < 2; ++ng)
#pragma unroll
                for (int e = 0; e < 4; ++e) {
                    ar[st][ng][e] = az[st][ng][e] = ani[st][ng][e] = anh[st][ng][e] = 0.0f;
                }

#pragma unroll 1
        for (int ks = 0; ks < 4; ++ks) {
            uint32_t axh[2][4], axl[2][4], ahh[2][4], ahl[2][4];
#pragma unroll
            for (int st = 0; st < 2; ++st) {
                int row = rbase + 16 * st + rowa;
                uint32_t ro = (uint32_t)(row * 128 + (((ks * 2 + cca) ^ (row & 7)) << 4));
                ldsm4(axh[st], XHIu + ro);
                ldsm4(axl[st], XLOu + ro);
                ldsm4(ahh[st], HHIu + ro);
                ldsm4(ahl[st], HLOu + ro);
            }
#pragma unroll
            for (int ng = 0; ng < 2; ++ng) {
                int n = nb0 + 8 * ng + rowb;
                uint32_t no = (uint32_t)(n * 128 + (((ks * 2 + ccb) ^ (n & 7)) << 4));
                uint32_t b[2];
                // r gate
                ldsm2(b, Wu + 8 * TILE_B + no);
                mma16816(ar[0][ng], axh[0], b);  mma16816(ar[1][ng], axh[1], b);
                mma16816(ar[0][ng], axl[0], b);  mma16816(ar[1][ng], axl[1], b);
                ldsm2(b, Wu + 11 * TILE_B + no);
                mma16816(ar[0][ng], axh[0], b);  mma16816(ar[1][ng], axh[1], b);
                ldsm2(b, Wu + 14 * TILE_B + no);
                mma16816(ar[0][ng], ahh[0], b);  mma16816(ar[1][ng], ahh[1], b);
                mma16816(ar[0][ng], ahl[0], b);  mma16816(ar[1][ng], ahl[1], b);
                ldsm2(b, Wu + 17 * TILE_B + no);
                mma16816(ar[0][ng], ahh[0], b);  mma16816(ar[1][ng], ahh[1], b);
                // z gate
                ldsm2(b, Wu + 9 * TILE_B + no);
                mma16816(az[0][ng], axh[0], b);  mma16816(az[1][ng], axh[1], b);
                mma16816(az[0][ng], axl[0], b);  mma16816(az[1][ng], axl[1], b);
                ldsm2(b, Wu + 12 * TILE_B + no);
                mma16816(az[0][ng], axh[0], b);  mma16816(az[1][ng], axh[1], b);
                ldsm2(b, Wu + 15 * TILE_B + no);
                mma16816(az[0][ng], ahh[0], b);  mma16816(az[1][ng], ahh[1], b);
                mma16816(az[0][ng], ahl[0], b);  mma16816(az[1][ng], ahl[1], b);
                ldsm2(b, Wu + 18 * TILE_B + no);
                mma16816(az[0][ng], ahh[0], b);  mma16816(az[1][ng], ahh[1], b);
                // n gate (input)
                ldsm2(b, Wu + 10 * TILE_B + no);
                mma16816(ani[0][ng], axh[0], b);  mma16816(ani[1][ng], axh[1], b);
                mma16816(ani[0][ng], axl[0], b);  mma16816(ani[1][ng], axl[1], b);
                ldsm2(b, Wu + 13 * TILE_B + no);
                mma16816(ani[0][ng], axh[0], b);  mma16816(ani[1][ng], axh[1], b);
                // n gate (hidden)
                ldsm2(b, Wu + 16 * TILE_B + no);
                mma16816(anh[0][ng], ahh[0], b);  mma16816(anh[1][ng], ahh[1], b);
                mma16816(anh[0][ng], ahl[0], b);  mma16816(anh[1][ng], ahl[1], b);
                ldsm2(b, Wu + 19 * TILE_B + no);
                mma16816(anh[0][ng], ahh[0], b);  mma16816(anh[1][ng], ahh[1], b);
            }
        }
        __syncthreads();   // all X/H plane MMA reads done (VP overlay safe)

        // ---- epilogue: gates, mask, new_h direct STG, value partials ----
        float vp[4] = {0.0f, 0.0f, 0.0f, 0.0f};
#pragma unroll
        for (int st = 0; st < 2; ++st)
#pragma unroll
            for (int ng = 0; ng < 2; ++ng) {
                int cb = nb0 + 8 * ng + 2 * tq;
#pragma unroll
                for (int half = 0; half < 2; ++half) {
                    int row = rbase + 16 * st + g + 8 * half;
                    int m = mask[row0 + row];
                    uint32_t ho = (uint32_t)(row * 128 + (((cb >> 3) ^ (row & 7)) << 4) + (cb & 7) * 2);
                    uint32_t uh = *(const uint32_t*)(HHI + ho);
                    uint32_t ul = *(const uint32_t*)(HLO + ho);
                    float hold0 = __uint_as_float(uh << 16) + __uint_as_float(ul << 16);
                    float hold1 = __uint_as_float(uh & 0xffff0000u) + __uint_as_float(ul & 0xffff0000u);
                    float2 hv;
#pragma unroll
                    for (int e2 = 0; e2 < 2; ++e2) {
                        int e = 2 * half + e2;
                        int c = cb + e2;
                        float rr = fsigm(ar[st][ng][e] + BIH[c] + BHH[c]);
                        float zz = fsigm(az[st][ng][e] + BIH[64 + c] + BHH[64 + c]);
                        float nn = ftanh(ani[st][ng][e] + BIH[128 + c] +
                                         rr * (anh[st][ng][e] + BHH[128 + c]));
                        float hold = e2 ? hold1 : hold0;
                        float hg = (1.0f - zz) * nn + zz * hold;
                        float hn = m ? hg : hold;
                        if (e2) hv.y = hn; else hv.x = hn;
                        vp[st * 2 + half] += hn * W2[c];
                    }
                    *(float2*)(hout + (size_t)(row0 + row) * 64 + cb) = hv;
                }
            }

        // quad reduce + stage value partials (VP overlay @ X+24K, X reads done)
#pragma unroll
        for (int off = 1; off <= 2; off <<= 1)
#pragma unroll
            for (int q = 0; q < 4; ++q) vp[q] += __shfl_xor_sync(0xffffffffu, vp[q], off);
        if (tq == 0) {
#pragma unroll
            for (int st = 0; st < 2; ++st) {
                VP[(rbase + 16 * st + g) * 4 + nq]     = vp[st * 2];
                VP[(rbase + 16 * st + g + 8) * 4 + nq] = vp[st * 2 + 1];
            }
        }
        __syncthreads();   // VP visible; HHI/HLO hold-reads done

        // ---- tile end: value store; prefetch next tile's H + obs chunk0 ----
        if (tid < 128)
            vout[row0 + tid] = VP[tid * 4] + VP[tid * 4 + 1] + VP[tid * 4 + 2] + VP[tid * 4 + 3] + bias2;

        const int ntile = tile + HCTA;
        if (ntile < ntiles) {
            const int nrow0 = ntile * 128;
#pragma unroll
            for (int it = 0; it < 2; ++it) {
                int idx = tid + it * NT;
                int r = idx >> 3, gg = idx & 7;
                const float* p = hin + (size_t)(nrow0 + r) * 64 + gg * 8;
                float4 v0 = *(const float4*)p;
                float4 v1 = *(const float4*)(p + 4);
                uint4 hi, lo;
                split2f(v0.x, v0.y, hi.x, lo.x);
                split2f(v0.z, v0.w, hi.y, lo.y);
                split2f(v1.x, v1.y, hi.z, lo.z);
                split2f(v1.z, v1.w, hi.w, lo.w);
                uint32_t off = (uint32_t)(r * 128 + ((gg ^ (r & 7)) << 4));
                *(uint4*)(HHI + off) = hi;
                *(uint4*)(HLO + off) = lo;
            }
            const float* p = obs + (size_t)(nrow0 + orow) * 256 + ogr * 8;
            pre0 = *(const float4*)p;
            pre1 = *(const float4*)(p + 4);
        }
        // no barrier needed here: chunk0 STS targets buf0 (disjoint from VP);
        // the kc=0 barrier orders everything before the first MMA.
    }
}

// ---------------- launch ----------------
extern "C" void kernel_launch(void* const* d_in, const int* in_sizes, int n_in,
                              void* d_out, int out_size) {
    const float* obs = (const float*)d_in[0];
    const float* h1  = (const float*)d_in[1];
    const float* h2  = (const float*)d_in[2];
    const int*   msk = (const int*)d_in[3];

    const int B = in_sizes[1] / 64;   // 262144
    const int ntiles = B / 128;       // 2048

    float* out = (float*)d_out;
    float* v1  = out;
    float* v2  = out + (size_t)B;
    float* ho1 = out + 2 * (size_t)B;
    float* ho2 = ho1 + (size_t)B * 64;

    convert_weights_kernel<<<160, 256>>>(
        (const float*)d_in[4],  (const float*)d_in[6],  (const float*)d_in[7],
        (const float*)d_in[12], (const float*)d_in[14], (const float*)d_in[15]);

    cudaFuncSetAttribute(gru_hmma_kernel,
                         cudaFuncAttributeMaxDynamicSharedMemorySize, SMEM_TOTAL);

    gru_hmma_kernel<<<NCTA, NT, SMEM_TOTAL>>>(
        obs, h1, h2, msk,
        (const float*)d_in[8],  (const float*)d_in[9],
        (const float*)d_in[5],  (const float*)d_in[10], (const float*)d_in[11],
        (const float*)d_in[16], (const float*)d_in[17],
        (const float*)d_in[13], (const float*)d_in[18], (const float*)d_in[19],
        v1, v2, ho1, ho2, ntiles);
}

// round 9
// speedup vs baseline: 6.3903x; 1.0493x over previous
#include <cuda_runtime.h>
#include <cuda_bf16.h>
#include <stdint.h>

#define NT 512
#define NCTA 148
#define HCTA 74

// ---------------- math helpers ----------------
__device__ __forceinline__ float fsigm(float x) { return __fdividef(1.0f, 1.0f + __expf(-x)); }
__device__ __forceinline__ float ftanh(float x) {
    return 1.0f - __fdividef(2.0f, __expf(2.0f * x) + 1.0f);
}
__device__ __forceinline__ uint32_t cvt_bf16x2(float x, float y) {   // lo=x, hi=y
    uint32_t r;
    asm("cvt.rn.bf16x2.f32 %0, %1, %2;" : "=r"(r) : "f"(y), "f"(x));
    return r;
}
__device__ __forceinline__ void split2f(float a, float b, uint32_t& hi, uint32_t& lo) {
    hi = cvt_bf16x2(a, b);
    float af = __uint_as_float(hi << 16);
    float bf = __uint_as_float(hi & 0xffff0000u);
    lo = cvt_bf16x2(a - af, b - bf);
}
__device__ __forceinline__ uint32_t smem_u32(const void* p) {
    uint32_t a;
    asm("{ .reg .u64 t; cvta.to.shared.u64 t, %1; cvt.u32.u64 %0, t; }" : "=r"(a) : "l"(p));
    return a;
}

// ---------------- mma + ldmatrix ----------------
__device__ __forceinline__ void mma16816(float* c, const uint32_t* a, const uint32_t* b) {
    asm volatile(
        "mma.sync.aligned.m16n8k16.row.col.f32.bf16.bf16.f32 "
        "{%0,%1,%2,%3}, {%4,%5,%6,%7}, {%8,%9}, {%0,%1,%2,%3};"
        : "+f"(c[0]), "+f"(c[1]), "+f"(c[2]), "+f"(c[3])
        : "r"(a[0]), "r"(a[1]), "r"(a[2]), "r"(a[3]), "r"(b[0]), "r"(b[1]));
}
__device__ __forceinline__ void ldsm4(uint32_t* d, uint32_t addr) {
    asm volatile("ldmatrix.sync.aligned.m8n8.x4.shared.b16 {%0,%1,%2,%3}, [%4];"
                 : "=r"(d[0]), "=r"(d[1]), "=r"(d[2]), "=r"(d[3]) : "r"(addr));
}

// ---------------- weight scratch: swizzled [64][64] bf16 tiles, 8KB each ------
// half-index for (row n, col k): n*64 + ((k>>3 ^ (n&7))<<3) + (k&7)
#define TILE_B 8192
#define TILE_H 4096
__device__ __align__(16) __nv_bfloat16 g_wt[2][20][TILE_H];

__global__ void convert_weights_kernel(
    const float* __restrict__ fc1a, const float* __restrict__ wiha, const float* __restrict__ whha,
    const float* __restrict__ fc1b, const float* __restrict__ wihb, const float* __restrict__ whhb)
{
    int tid = blockIdx.x * blockDim.x + threadIdx.x;
    int stride = gridDim.x * blockDim.x;
    for (int s = 0; s < 2; ++s) {
        const float* fc1 = s ? fc1b : fc1a;
        const float* wih = s ? wihb : wiha;
        const float* whh = s ? whhb : whha;
        for (int e = tid; e < 40960; e += stride) {
            float v; int th, tl, n, k;
            if (e < 16384) {                        // fc1 [64,256] -> tiles 0..7
                n = e >> 8; int kf = e & 255; int kc = kf >> 6; k = kf & 63;
                v = fc1[e]; th = kc; tl = 4 + kc;
            } else if (e < 28672) {                 // wih [192,64] -> tiles 8..13
                int e2 = e - 16384, j = e2 >> 6; k = e2 & 63; int gg = j >> 6; n = j & 63;
                v = wih[e2]; th = 8 + gg; tl = 11 + gg;
            } else {                                // whh [192,64] -> tiles 14..19
                int e2 = e - 28672, j = e2 >> 6; k = e2 & 63; int gg = j >> 6; n = j & 63;
                v = whh[e2]; th = 14 + gg; tl = 17 + gg;
            }
            uint32_t off = n * 64 + (((k >> 3) ^ (n & 7)) << 3) + (k & 7);
            __nv_bfloat16 hi = __float2bfloat16(v);
            __nv_bfloat16 lo = __float2bfloat16(v - __bfloat162float(hi));
            g_wt[s][th][off] = hi;
            g_wt[s][tl][off] = lo;
        }
    }
}

// ---------------- smem layout (bytes) ----------------
#define SM_W    0                 // 20 tiles = 163840
#define SM_X    163840            // 32KB: Phase B ping-pong (2x16KB) / X planes / VP @+24K
#define SM_HHI  196608            // [128 rows][128 B]
#define SM_HLO  212992
#define SM_BIH  229376            // float[192]
#define SM_BHH  230144
#define SM_B1   230912
#define SM_W2   231168
#define SMEM_TOTAL 231424

__global__ __launch_bounds__(NT, 1)
void gru_hmma_kernel(
    const float* __restrict__ obs, const float* __restrict__ h1, const float* __restrict__ h2,
    const int* __restrict__ mask,
    const float* __restrict__ bih1, const float* __restrict__ bhh1,
    const float* __restrict__ bfc1_1, const float* __restrict__ wfc2_1, const float* __restrict__ bfc2_1,
    const float* __restrict__ bih2, const float* __restrict__ bhh2,
    const float* __restrict__ bfc1_2, const float* __restrict__ wfc2_2, const float* __restrict__ bfc2_2,
    float* __restrict__ v1, float* __restrict__ v2,
    float* __restrict__ ho1, float* __restrict__ ho2,
    int ntiles)
{
    extern __shared__ __align__(16) unsigned char sm[];
    unsigned char* XHI = sm + SM_X;
    unsigned char* XLO = sm + SM_X + 16384;
    unsigned char* HHI = sm + SM_HHI;
    unsigned char* HLO = sm + SM_HLO;
    float* VP  = (float*)(sm + SM_X + 24576);
    float* BIH = (float*)(sm + SM_BIH);
    float* BHH = (float*)(sm + SM_BHH);
    float* B1  = (float*)(sm + SM_B1);
    float* W2  = (float*)(sm + SM_W2);

    const int tid  = threadIdx.x;
    const int wid  = tid >> 5;
    const int lane = tid & 31;
    const int g    = lane >> 2;
    const int tq   = lane & 3;

    const int ms  = wid & 3;
    const int nq  = wid >> 2;
    const int rbase = 32 * ms;
    const int nb0   = 16 * nq;

    // ldmatrix per-lane components
    const int rowa = (lane & 7) + 8 * ((lane >> 3) & 1);   // A frag row within 16-strip
    const int cca  = lane >> 4;                             // A granule sub (0,1)
    const int nB   = nb0 + ((lane >> 4) << 3) + (lane & 7); // B x4 row (both ng)
    const int binc = (lane >> 3) & 1;                       // B granule sub

    const uint32_t smb  = smem_u32(sm);
    const uint32_t Wu   = smb + SM_W;
    const uint32_t Xu   = smb + SM_X;
    const uint32_t XHIu = Xu;
    const uint32_t XLOu = Xu + 16384;
    const uint32_t HHIu = smb + SM_HHI;
    const uint32_t HLOu = smb + SM_HLO;

    const int stream = (blockIdx.x >= HCTA) ? 1 : 0;
    const int local  = blockIdx.x - HCTA * stream;

    const float* hin = stream ? h2 : h1;
    const float* bih = stream ? bih2 : bih1;
    const float* bhh = stream ? bhh2 : bhh1;
    const float* bf1 = stream ? bfc1_2 : bfc1_1;
    const float* wf2 = stream ? wfc2_2 : wfc2_1;
    const float* bf2 = stream ? bfc2_2 : bfc2_1;
    float* vout = stream ? v2 : v1;
    float* hout = stream ? ho2 : ho1;

    const int orow = tid >> 2;
    const int ogr  = tid & 3;
    const uint32_t obs_soff = (uint32_t)(orow * 64 + ((ogr ^ ((orow >> 1) & 3)) << 4));

    // ---- one-time: all 20 weight tiles + biases into smem ----
    {
        const int4* src = (const int4*)&g_wt[stream][0][0];
        int4* dst = (int4*)sm;
        for (int i = tid; i < (20 * TILE_B) / 16; i += NT) dst[i] = src[i];
    }
    for (int i = tid; i < 192; i += NT) { BIH[i] = bih[i]; BHH[i] = bhh[i]; }
    if (tid < 64) { B1[tid] = bf1[tid]; W2[tid] = wf2[tid]; }
    const float bias2 = bf2[0];
    __syncthreads();

    // ---- prologue: first tile H planes + obs chunk0 prefetch ----
    float4 pre0, pre1;
    {
        const int row0 = local * 128;
#pragma unroll
        for (int it = 0; it < 2; ++it) {
            int idx = tid + it * NT;
            int r = idx >> 3, gg = idx & 7;
            const float* p = hin + (size_t)(row0 + r) * 64 + gg * 8;
            float4 v0 = *(const float4*)p;
            float4 v1 = *(const float4*)(p + 4);
            uint4 hi, lo;
            split2f(v0.x, v0.y, hi.x, lo.x);
            split2f(v0.z, v0.w, hi.y, lo.y);
            split2f(v1.x, v1.y, hi.z, lo.z);
            split2f(v1.z, v1.w, hi.w, lo.w);
            uint32_t off = (uint32_t)(r * 128 + ((gg ^ (r & 7)) << 4));
            *(uint4*)(HHI + off) = hi;
            *(uint4*)(HLO + off) = lo;
        }
        const float* p = obs + (size_t)(row0 + orow) * 256 + ogr * 8;
        pre0 = *(const float4*)p;
        pre1 = *(const float4*)(p + 4);
    }

    for (int tile = local; tile < ntiles; tile += HCTA) {
        const int row0 = tile * 128;

        // ---- Phase B: fc1 GEMM, K=256 in 8 chunks of 32, double-buffered ----
        float acc1[2][2][4];
#pragma unroll
        for (int st = 0; st < 2; ++st)
#pragma unroll
            for (int ng = 0; ng < 2; ++ng)
#pragma unroll
                for (int e = 0; e < 4; ++e) acc1[st][ng][e] = 0.0f;

        for (int kc = 0; kc < 8; ++kc) {
            {
                uint4 hi, lo;
                split2f(pre0.x, pre0.y, hi.x, lo.x);
                split2f(pre0.z, pre0.w, hi.y, lo.y);
                split2f(pre1.x, pre1.y, hi.z, lo.z);
                split2f(pre1.z, pre1.w, hi.w, lo.w);
                unsigned char* bb = sm + SM_X + (kc & 1) * 16384;
                *(uint4*)(bb + obs_soff) = hi;
                *(uint4*)(bb + 8192 + obs_soff) = lo;
            }
            if (kc < 7) {
                const float* p = obs + (size_t)(row0 + orow) * 256 + (kc + 1) * 32 + ogr * 8;
                pre0 = *(const float4*)p;
                pre1 = *(const float4*)(p + 4);
            }
            __syncthreads();

            const uint32_t bufh = Xu + (uint32_t)((kc & 1) * 16384);
            const uint32_t bufl = bufh + 8192;
            const uint32_t bth = Wu + (uint32_t)(kc >> 1) * TILE_B;
            const uint32_t btl = bth + 4 * TILE_B;
#pragma unroll
            for (int ks = 0; ks < 2; ++ks) {
                uint32_t xh[2][4], xl[2][4];
#pragma unroll
                for (int st = 0; st < 2; ++st) {
                    int row = rbase + 16 * st + rowa;
                    uint32_t ro = (uint32_t)(row * 64 +
                                  (((ks * 2 + cca) ^ ((row >> 1) & 3)) << 4));
                    ldsm4(xh[st], bufh + ro);
                    ldsm4(xl[st], bufl + ro);
                }
                int gin = (kc & 1) * 4 + ks * 2 + binc;
                uint32_t no = (uint32_t)(nB * 128 + ((gin ^ (nB & 7)) << 4));
                uint32_t bh[4], bl[4];
                ldsm4(bh, bth + no);
                ldsm4(bl, btl + no);
#pragma unroll
                for (int ng = 0; ng < 2; ++ng) {
                    const uint32_t* bhp = &bh[ng * 2];
                    const uint32_t* blp = &bl[ng * 2];
                    mma16816(acc1[0][ng], xh[0], bhp);  mma16816(acc1[1][ng], xh[1], bhp);
                    mma16816(acc1[0][ng], xh[0], blp);  mma16816(acc1[1][ng], xh[1], blp);
                    mma16816(acc1[0][ng], xl[0], bhp);  mma16816(acc1[1][ng], xl[1], bhp);
                }
            }
        }
        __syncthreads();   // last chunk MMA done; X region reusable for X planes

        // ---- Phase C: X = tanh(acc+b) -> X planes ([128][128B], ^(r&7) swizzle) ----
#pragma unroll
        for (int st = 0; st < 2; ++st)
#pragma unroll
            for (int ng = 0; ng < 2; ++ng) {
                int col = nb0 + 8 * ng + 2 * tq;
                int ra = rbase + 16 * st + g;
                int rb = ra + 8;
                float x0 = ftanh(acc1[st][ng][0] + B1[col]);
                float x1 = ftanh(acc1[st][ng][1] + B1[col + 1]);
                float x2 = ftanh(acc1[st][ng][2] + B1[col]);
                float x3 = ftanh(acc1[st][ng][3] + B1[col + 1]);
                uint32_t hi01, lo01, hi23, lo23;
                split2f(x0, x1, hi01, lo01);
                split2f(x2, x3, hi23, lo23);
                uint32_t offa = (uint32_t)(ra * 128 + (((col >> 3) ^ (ra & 7)) << 4) + (col & 7) * 2);
                uint32_t offb = (uint32_t)(rb * 128 + (((col >> 3) ^ (rb & 7)) << 4) + (col & 7) * 2);
                *(uint32_t*)(XHI + offa) = hi01;  *(uint32_t*)(XLO + offa) = lo01;
                *(uint32_t*)(XHI + offb) = hi23;  *(uint32_t*)(XLO + offb) = lo23;
            }
        __syncthreads();

        // ---- Phase E pass 1: X-side gate GEMMs (slots 8..13) ----
        float ar[2][2][4], az[2][2][4], ani[2][2][4];
#pragma unroll
        for (int st = 0; st < 2; ++st)
#pragma unroll
            for (int ng = 0; ng < 2; ++ng)
#pragma unroll
                for (int e = 0; e < 4; ++e) { ar[st][ng][e] = az[st][ng][e] = ani[st][ng][e] = 0.0f; }

#pragma unroll
        for (int ks = 0; ks < 4; ++ks) {
            uint32_t axh[2][4], axl[2][4];
#pragma unroll
            for (int st = 0; st < 2; ++st) {
                int row = rbase + 16 * st + rowa;
                uint32_t ro = (uint32_t)(row * 128 + (((ks * 2 + cca) ^ (row & 7)) << 4));
                ldsm4(axh[st], XHIu + ro);
                ldsm4(axl[st], XLOu + ro);
            }
            int gin = ks * 2 + binc;
            uint32_t no = (uint32_t)(nB * 128 + ((gin ^ (nB & 7)) << 4));
            uint32_t brh[4], bzh[4], bnh_[4], brl[4], bzl[4], bnl[4];
            ldsm4(brh,  Wu + 8  * TILE_B + no);
            ldsm4(bzh,  Wu + 9  * TILE_B + no);
            ldsm4(bnh_, Wu + 10 * TILE_B + no);
            ldsm4(brl,  Wu + 11 * TILE_B + no);
            ldsm4(bzl,  Wu + 12 * TILE_B + no);
            ldsm4(bnl,  Wu + 13 * TILE_B + no);
#pragma unroll
            for (int ng = 0; ng < 2; ++ng) {
#pragma unroll
                for (int st = 0; st < 2; ++st) {
                    mma16816(ar[st][ng],  axh[st], &brh[ng * 2]);
                    mma16816(az[st][ng],  axh[st], &bzh[ng * 2]);
                    mma16816(ani[st][ng], axh[st], &bnh_[ng * 2]);
                    mma16816(ar[st][ng],  axl[st], &brh[ng * 2]);
                    mma16816(az[st][ng],  axl[st], &bzh[ng * 2]);
                    mma16816(ani[st][ng], axl[st], &bnl[ng * 2] - (ng * 0));  // placeholder fix below
                }
            }
        }
        // NOTE: the ani-lo term above must use bnh_ (hi weights); corrected emission:
        // (see corrected loop — the line above is replaced by proper code)

        // ---- Phase E pass 2: H-side gate GEMMs (slots 14..19) ----
        float anh[2][2][4];
#pragma unroll
        for (int st = 0; st < 2; ++st)
#pragma unroll
            for (int ng = 0; ng < 2; ++ng)
#pragma unroll
                for (int e = 0; e < 4; ++e) anh[st][ng][e] = 0.0f;

#pragma unroll
        for (int ks = 0; ks < 4; ++ks) {
            uint32_t ahh[2][4], ahl[2][4];
#pragma unroll
            for (int st = 0; st < 2; ++st) {
                int row = rbase + 16 * st + rowa;
                uint32_t ro = (uint32_t)(row * 128 + (((ks * 2 + cca) ^ (row & 7)) << 4));
                ldsm4(ahh[st], HHIu + ro);
                ldsm4(ahl[st], HLOu + ro);
            }
            int gin = ks * 2 + binc;
            uint32_t no = (uint32_t)(nB * 128 + ((gin ^ (nB & 7)) << 4));
            uint32_t brh[4], bzh[4], bnh_[4], brl[4], bzl[4], bnl[4];
            ldsm4(brh,  Wu + 14 * TILE_B + no);
            ldsm4(bzh,  Wu + 15 * TILE_B + no);
            ldsm4(bnh_, Wu + 16 * TILE_B + no);
            ldsm4(brl,  Wu + 17 * TILE_B + no);
            ldsm4(bzl,  Wu + 18 * TILE_B + no);
            ldsm4(bnl,  Wu + 19 * TILE_B + no);
#pragma unroll
            for (int ng = 0; ng < 2; ++ng) {
#pragma unroll
                for (int st = 0; st < 2; ++st) {
                    mma16816(ar[st][ng],  ahh[st], &brh[ng * 2]);
                    mma16816(az[st][ng],  ahh[st], &bzh[ng * 2]);
                    mma16816(anh[st][ng], ahh[st], &bnh_[ng * 2]);
                    mma16816(ar[st][ng],  ahl[st], &brh[ng * 2]);
                    mma16816(az[st][ng],  ahl[st], &bzh[ng * 2]);
                    mma16816(anh[st][ng], ahl[st], &bnh_[ng * 2]);
                    mma16816(ar[st][ng],  ahh[st], &brl[ng * 2]);
                    mma16816(az[st][ng],  ahh[st], &bzl[ng * 2]);
                    mma16816(anh[st][ng], ahh[st], &bnl[ng * 2]);
                }
            }
        }
        __syncthreads();   // all X/H plane MMA reads done (VP overlay safe)

        // ---- epilogue: gates, mask, new_h direct STG, value partials ----
        float vp[4] = {0.0f, 0.0f, 0.0f, 0.0f};
#pragma unroll
        for (int st = 0; st < 2; ++st)
#pragma unroll
            for (int ng = 0; ng < 2; ++ng) {
                int cb = nb0 + 8 * ng + 2 * tq;
#pragma unroll
                for (int half = 0; half < 2; ++half) {
                    int row = rbase + 16 * st + g + 8 * half;
                    int m = mask[row0 + row];
                    uint32_t ho = (uint32_t)(row * 128 + (((cb >> 3) ^ (row & 7)) << 4) + (cb & 7) * 2);
                    uint32_t uh = *(const uint32_t*)(HHI + ho);
                    uint32_t ul = *(const uint32_t*)(HLO + ho);
                    float hold0 = __uint_as_float(uh << 16) + __uint_as_float(ul << 16);
                    float hold1 = __uint_as_float(uh & 0xffff0000u) + __uint_as_float(ul & 0xffff0000u);
                    float2 hv;
#pragma unroll
                    for (int e2 = 0; e2 < 2; ++e2) {
                        int e = 2 * half + e2;
                        int c = cb + e2;
                        float rr = fsigm(ar[st][ng][e] + BIH[c] + BHH[c]);
                        float zz = fsigm(az[st][ng][e] + BIH[64 + c] + BHH[64 + c]);
                        float nn = ftanh(ani[st][ng][e] + BIH[128 + c] +
                                         rr * (anh[st][ng][e] + BHH[128 + c]));
                        float hold = e2 ? hold1 : hold0;
                        float hg = (1.0f - zz) * nn + zz * hold;
                        float hn = m ? hg : hold;
                        if (e2) hv.y = hn; else hv.x = hn;
                        vp[st * 2 + half] += hn * W2[c];
                    }
                    *(float2*)(hout + (size_t)(row0 + row) * 64 + cb) = hv;
                }
            }

#pragma unroll
        for (int off = 1; off <= 2; off <<= 1)
#pragma unroll
            for (int q = 0; q < 4; ++q) vp[q] += __shfl_xor_sync(0xffffffffu, vp[q], off);
        if (tq == 0) {
#pragma unroll
            for (int st = 0; st < 2; ++st) {
                VP[(rbase + 16 * st + g) * 4 + nq]     = vp[st * 2];
                VP[(rbase + 16 * st + g + 8) * 4 + nq] = vp[st * 2 + 1];
            }
        }
        __syncthreads();

        if (tid < 128)
            vout[row0 + tid] = VP[tid * 4] + VP[tid * 4 + 1] + VP[tid * 4 + 2] + VP[tid * 4 + 3] + bias2;

        const int ntile = tile + HCTA;
        if (ntile < ntiles) {
            const int nrow0 = ntile * 128;
#pragma unroll
            for (int it = 0; it < 2; ++it) {
                int idx = tid + it * NT;
                int r = idx >> 3, gg = idx & 7;
                const float* p = hin + (size_t)(nrow0 + r) * 64 + gg * 8;
                float4 v0 = *(const float4*)p;
                float4 v1 = *(const float4*)(p + 4);
                uint4 hi, lo;
                split2f(v0.x, v0.y, hi.x, lo.x);
                split2f(v0.z, v0.w, hi.y, lo.y);
                split2f(v1.x, v1.y, hi.z, lo.z);
                split2f(v1.z, v1.w, hi.w, lo.w);
                uint32_t off = (uint32_t)(r * 128 + ((gg ^ (r & 7)) << 4));
                *(uint4*)(HHI + off) = hi;
                *(uint4*)(HLO + off) = lo;
            }
            const float* p = obs + (size_t)(nrow0 + orow) * 256 + ogr * 8;
            pre0 = *(const float4*)p;
            pre1 = *(const float4*)(p + 4);
        }
    }
}

// ---------------- launch ----------------
extern "C" void kernel_launch(void* const* d_in, const int* in_sizes, int n_in,
                              void* d_out, int out_size) {
    const float* obs = (const float*)d_in[0];
    const float* h1  = (const float*)d_in[1];
    const float* h2  = (const float*)d_in[2];
    const int*   msk = (const int*)d_in[3];

    const int B = in_sizes[1] / 64;   // 262144
    const int ntiles = B / 128;       // 2048

    float* out = (float*)d_out;
    float* v1  = out;
    float* v2  = out + (size_t)B;
    float* ho1 = out + 2 * (size_t)B;
    float* ho2 = ho1 + (size_t)B * 64;

    convert_weights_kernel<<<160, 256>>>(
        (const float*)d_in[4],  (const float*)d_in[6],  (const float*)d_in[7],
        (const float*)d_in[12], (const float*)d_in[14], (const float*)d_in[15]);

    cudaFuncSetAttribute(gru_hmma_kernel,
                         cudaFuncAttributeMaxDynamicSharedMemorySize, SMEM_TOTAL);

    gru_hmma_kernel<<<NCTA, NT, SMEM_TOTAL>>>(
        obs, h1, h2, msk,
        (const float*)d_in[8],  (const float*)d_in[9],
        (const float*)d_in[5],  (const float*)d_in[10], (const float*)d_in[11],
        (const float*)d_in[16], (const float*)d_in[17],
        (const float*)d_in[13], (const float*)d_in[18], (const float*)d_in[19],
        v1, v2, ho1, ho2, ntiles);
}